// round 12
// baseline (speedup 1.0000x reference)
#include <cuda_runtime.h>

#define BB 4
#define CC 256
#define CI 128
#define NN 4096
#define BN_EPS 1e-5f

typedef unsigned int uint;
typedef unsigned short ushort;

// ---------------- scratch (no allocations allowed) ----------------
__device__ __align__(16) ushort g_Xh[BB * NN * CC];   // x^T hi [b][n][c]
__device__ __align__(16) ushort g_Xl[BB * NN * CC];
__device__ __align__(16) ushort g_PWh[3 * CI * CC];   // proj weights hi (g, theta, phi) [which][o][c]
__device__ __align__(16) ushort g_PWl[3 * CI * CC];
__device__ __align__(16) ushort g_Wwh[CC * CI];       // W conv weight hi [o][d]
__device__ __align__(16) ushort g_Wwl[CC * CI];
__device__ __align__(16) ushort g_Qh[BB * NN * CI];   // theta hi  [b][n][d]
__device__ __align__(16) ushort g_Ql[BB * NN * CI];
__device__ __align__(16) ushort g_Kh[BB * NN * CI];   // phi hi    [b][m][d]
__device__ __align__(16) ushort g_Kl[BB * NN * CI];
__device__ __align__(16) ushort g_Gth[BB * CI * NN];  // g^T hi    [b][d][m]
__device__ __align__(16) ushort g_Yh[BB * NN * CI];   // attention out hi [b][n][d]
__device__ __align__(16) ushort g_Yl[BB * NN * CI];
__device__ __align__(16) float g_WY[BB * NN * CC];    // W conv out [b][n][o]
__device__ __align__(16) float g_psum[128 * CC];
__device__ __align__(16) float g_psq [128 * CC];
__device__ float g_mean[CC];
__device__ float g_rstd[CC];

// ---------------- helpers ----------------
__device__ __forceinline__ ushort bf16rn(float v) {
    uint u = __float_as_uint(v);
    return (ushort)((u + 0x7FFFu + ((u >> 16) & 1u)) >> 16);
}
__device__ __forceinline__ uint smem_u32(const void* p) {
    uint a;
    asm("{ .reg .u64 t; cvta.to.shared.u64 t, %1; cvt.u32.u64 %0, t; }" : "=r"(a) : "l"(p));
    return a;
}
__device__ __forceinline__ void cpa16(uint s, const void* g) {
    asm volatile("cp.async.cg.shared.global [%0], [%1], 16;" :: "r"(s), "l"(g) : "memory");
}
#define CP_COMMIT() asm volatile("cp.async.commit_group;" ::: "memory")
#define CP_WAIT0()  asm volatile("cp.async.wait_group 0;" ::: "memory")
#define CP_WAIT1()  asm volatile("cp.async.wait_group 1;" ::: "memory")

#define LDSM4(r0, r1, r2, r3, addr) \
    asm volatile("ldmatrix.sync.aligned.m8n8.x4.shared.b16 {%0,%1,%2,%3}, [%4];" \
        : "=r"(r0), "=r"(r1), "=r"(r2), "=r"(r3) : "r"(addr))

// pack2(lo, hi): bf16x2 with lo in low half
__device__ __forceinline__ uint pack2(float lo, float hi) {
    uint r;
    asm("cvt.rn.bf16x2.f32 %0, %1, %2;" : "=r"(r) : "f"(hi), "f"(lo));
    return r;
}
__device__ __forceinline__ void mma_bf(float& d0, float& d1, float& d2, float& d3,
                                       uint a0, uint a1, uint a2, uint a3,
                                       uint b0, uint b1) {
    asm volatile("mma.sync.aligned.m16n8k16.row.col.f32.bf16.bf16.f32 "
        "{%0,%1,%2,%3},{%4,%5,%6,%7},{%8,%9},{%0,%1,%2,%3};"
        : "+f"(d0), "+f"(d1), "+f"(d2), "+f"(d3)
        : "r"(a0), "r"(a1), "r"(a2), "r"(a3), "r"(b0), "r"(b1));
}

// ---------------- kernel 0a: transpose + split x -> bf16 hi/lo [b][n][c] ----------------
__global__ void __launch_bounds__(256) xcvt_kernel(const float* __restrict__ x)
{
    __shared__ float st[64 * 65];
    const int n0 = blockIdx.x * 64;
    const int c0 = blockIdx.y * 64;
    const int b  = blockIdx.z;
    const int tid = threadIdx.x;
#pragma unroll
    for (int r = 0; r < 16; r++) {
        int idx = tid + r * 256;
        int cc = idx >> 6, nl = idx & 63;
        st[nl * 65 + cc] = x[((size_t)(b * CC + c0 + cc)) * NN + n0 + nl];
    }
    __syncthreads();
#pragma unroll
    for (int r = 0; r < 16; r++) {
        int idx = tid + r * 256;
        int nl = idx >> 6, cc = idx & 63;
        float v = st[nl * 65 + cc];
        ushort h = bf16rn(v);
        ushort l = bf16rn(v - __uint_as_float(((uint)h) << 16));
        size_t o = ((size_t)(b * NN + n0 + nl)) * CC + c0 + cc;
        g_Xh[o] = h;
        g_Xl[o] = l;
    }
}

// ---------------- kernel 0b: split weights -> bf16 hi/lo ----------------
__global__ void __launch_bounds__(256) wcvt_kernel(
    const float* __restrict__ gw, const float* __restrict__ tw,
    const float* __restrict__ pw, const float* __restrict__ Ww)
{
    const int total = 3 * CI * CC + CC * CI;
    for (int idx = blockIdx.x * 256 + threadIdx.x; idx < total; idx += gridDim.x * 256) {
        float v;
        if (idx < 3 * CI * CC) {
            int which = idx / (CI * CC), r = idx % (CI * CC);
            v = (which == 0 ? gw : which == 1 ? tw : pw)[r];
            ushort h = bf16rn(v);
            g_PWh[idx] = h;
            g_PWl[idx] = bf16rn(v - __uint_as_float(((uint)h) << 16));
        } else {
            int r = idx - 3 * CI * CC;
            v = Ww[r];
            ushort h = bf16rn(v);
            g_Wwh[r] = h;
            g_Wwl[r] = bf16rn(v - __uint_as_float(((uint)h) << 16));
        }
    }
}

// ---------------- kernel 1: mma projections ----------------
#define PJ_XH(buf) ((buf) * 73728)
#define PJ_XL(buf) ((buf) * 73728 + 18432)
#define PJ_WH(buf) ((buf) * 73728 + 36864)
#define PJ_WL(buf) ((buf) * 73728 + 55296)
#define PROJ_SMEM (2 * 73728)

extern __shared__ char sm_p[];

__global__ void __launch_bounds__(256, 1) proj_kernel(
    const float* __restrict__ gb_, const float* __restrict__ tb_,
    const float* __restrict__ pb_)
{
    const int b  = blockIdx.y;
    const int n0 = blockIdx.x * 128;
    const int which = blockIdx.z;              // 0=g->Gt(hi only), 1=theta->Q, 2=phi->K
    const int tid = threadIdx.x;
    const int lane = tid & 31, warp = tid >> 5;
    const uint sb = smem_u32(sm_p);
    const float* bias = (which == 0) ? gb_ : (which == 1) ? tb_ : pb_;

    const char* Xh_g = (const char*)(g_Xh + (size_t)(b * NN + n0) * CC);
    const char* Xl_g = (const char*)(g_Xl + (size_t)(b * NN + n0) * CC);
    const char* Wh_g = (const char*)(g_PWh + which * CI * CC);
    const char* Wl_g = (const char*)(g_PWl + which * CI * CC);

    auto load_chunk = [&](int ch) {
        if (ch < 4) {
            int buf = ch & 1;
            int cb = ch * 128;
#pragma unroll
            for (int it = 0; it < 4; it++) {
                int u = tid + it * 256;
                int row = u >> 3, seg = u & 7;
                cpa16(sb + PJ_XH(buf) + row * 144 + seg * 16, Xh_g + (size_t)row * 512 + cb + seg * 16);
                cpa16(sb + PJ_XL(buf) + row * 144 + seg * 16, Xl_g + (size_t)row * 512 + cb + seg * 16);
                cpa16(sb + PJ_WH(buf) + row * 144 + seg * 16, Wh_g + (size_t)row * 512 + cb + seg * 16);
                cpa16(sb + PJ_WL(buf) + row * 144 + seg * 16, Wl_g + (size_t)row * 512 + cb + seg * 16);
            }
        }
        CP_COMMIT();
    };

    load_chunk(0);
    load_chunk(1);

    const int r0 = warp * 16 + (lane >> 2);
    float acc[16][4];
#pragma unroll
    for (int i = 0; i < 16; i++)
#pragma unroll
        for (int c = 0; c < 4; c++) acc[i][c] = 0.f;

    const uint qoff144 = (uint)(warp * 16 + (lane & 15)) * 144 + ((lane >> 4) << 4);
    const uint koff144 = (uint)((lane & 7) + ((lane >> 4) << 3)) * 144 + (((lane >> 3) & 1) << 4);

    for (int ch = 0; ch < 4; ch++) {
        CP_WAIT1();
        __syncthreads();
        int buf = ch & 1;
#pragma unroll
        for (int kt = 0; kt < 4; kt++) {
            uint ah0, ah1, ah2, ah3, al0, al1, al2, al3;
            LDSM4(ah0, ah1, ah2, ah3, sb + PJ_XH(buf) + qoff144 + kt * 32);
            LDSM4(al0, al1, al2, al3, sb + PJ_XL(buf) + qoff144 + kt * 32);
#pragma unroll
            for (int op = 0; op < 8; op++) {
                uint bh0, bh1, bh2, bh3, bl0, bl1, bl2, bl3;
                LDSM4(bh0, bh1, bh2, bh3, sb + PJ_WH(buf) + koff144 + (uint)op * 16 * 144 + kt * 32);
                LDSM4(bl0, bl1, bl2, bl3, sb + PJ_WL(buf) + koff144 + (uint)op * 16 * 144 + kt * 32);
                mma_bf(acc[2*op][0], acc[2*op][1], acc[2*op][2], acc[2*op][3],
                       ah0, ah1, ah2, ah3, bh0, bh1);
                mma_bf(acc[2*op][0], acc[2*op][1], acc[2*op][2], acc[2*op][3],
                       ah0, ah1, ah2, ah3, bl0, bl1);
                mma_bf(acc[2*op][0], acc[2*op][1], acc[2*op][2], acc[2*op][3],
                       al0, al1, al2, al3, bh0, bh1);
                mma_bf(acc[2*op+1][0], acc[2*op+1][1], acc[2*op+1][2], acc[2*op+1][3],
                       ah0, ah1, ah2, ah3, bh2, bh3);
                mma_bf(acc[2*op+1][0], acc[2*op+1][1], acc[2*op+1][2], acc[2*op+1][3],
                       ah0, ah1, ah2, ah3, bl2, bl3);
                mma_bf(acc[2*op+1][0], acc[2*op+1][1], acc[2*op+1][2], acc[2*op+1][3],
                       al0, al1, al2, al3, bh2, bh3);
            }
        }
        __syncthreads();
        load_chunk(ch + 2);
    }
    CP_WAIT0();

#pragma unroll
    for (int ot = 0; ot < 16; ot++) {
        int o = ot * 8 + (lane & 3) * 2;
        float b0 = bias[o], b1 = bias[o + 1];
        acc[ot][0] += b0; acc[ot][1] += b1;
        acc[ot][2] += b0; acc[ot][3] += b1;
    }

    if (which != 0) {
        uint* dh = (uint*)((which == 1) ? g_Qh : g_Kh) + (size_t)(b * NN + n0) * (CI / 2);
        uint* dl = (uint*)((which == 1) ? g_Ql : g_Kl) + (size_t)(b * NN + n0) * (CI / 2);
#pragma unroll
        for (int ot = 0; ot < 16; ot++) {
            uint i0 = (uint)r0 * 64 + ot * 4 + (lane & 3);
            uint i1 = i0 + 8 * 64;
            uint h0 = pack2(acc[ot][0], acc[ot][1]);
            uint h1 = pack2(acc[ot][2], acc[ot][3]);
            float e0 = acc[ot][0] - __uint_as_float(h0 << 16);
            float e1 = acc[ot][1] - __uint_as_float(h0 & 0xffff0000u);
            float e2 = acc[ot][2] - __uint_as_float(h1 << 16);
            float e3 = acc[ot][3] - __uint_as_float(h1 & 0xffff0000u);
            dh[i0] = h0; dl[i0] = pack2(e0, e1);
            dh[i1] = h1; dl[i1] = pack2(e2, e3);
        }
    } else {
        ushort* st = (ushort*)sm_p;
        __syncthreads();
#pragma unroll
        for (int ot = 0; ot < 16; ot++) {
            int o = ot * 8 + (lane & 3) * 2;
#pragma unroll
            for (int c = 0; c < 4; c++) {
                int oo = o + (c & 1);
                int rr = (c < 2) ? r0 : (r0 + 8);
                st[oo * 136 + rr] = bf16rn(acc[ot][c]);
            }
        }
        __syncthreads();
#pragma unroll
        for (int it = 0; it < 8; it++) {
            int u = tid + it * 256;
            int o = u >> 4, seg = u & 15;
            *(uint4*)((char*)g_Gth + (((size_t)(b * CI + o)) * NN + n0) * 2 + seg * 16)
                = *(const uint4*)((const char*)st + o * 272 + seg * 16);
        }
    }
}

// ---------------- kernel 2: flash attention (ldmatrix, 3-stage, cross-iter pipelined) ----------------
#define SQH 0
#define SQL 34816
#define SKH(s) (69632 + (s) * 34816)
#define SKL(s) (69632 + (s) * 34816 + 17408)
#define SGH(s) (174080 + (s) * 18432)
#define ATTN_SMEM 229376
#define KTILES 64

extern __shared__ char sm_a[];

__global__ void __launch_bounds__(256, 1) attn_kernel()
{
    const int b  = blockIdx.y;
    const int qt = blockIdx.x;
    const int tid = threadIdx.x;
    const int lane = tid & 31, warp = tid >> 5;
    const uint sb = smem_u32(sm_a);

    const size_t qbase = (size_t)(b * NN + qt * 128) * CI;
    const char* Qh_g = (const char*)(g_Qh + qbase);
    const char* Ql_g = (const char*)(g_Ql + qbase);
    const char* gh_g = (const char*)(g_Gth + (size_t)(b * CI) * NN);

    auto load_stage = [&](int kt, int s) {
        const char* khs = (const char*)(g_Kh + (size_t)(b * NN + kt * 64) * CI);
        const char* kls = (const char*)(g_Kl + (size_t)(b * NN + kt * 64) * CI);
#pragma unroll
        for (int it = 0; it < 4; it++) {
            int u = tid + it * 256;
            int row = u >> 4, ch = u & 15;
            cpa16(sb + SKH(s) + row * 272 + ch * 16, khs + row * 256 + ch * 16);
            cpa16(sb + SKL(s) + row * 272 + ch * 16, kls + row * 256 + ch * 16);
        }
#pragma unroll
        for (int it = 0; it < 4; it++) {
            int u = tid + it * 256;
            int row = u >> 3, ch = u & 7;
            cpa16(sb + SGH(s) + row * 144 + ch * 16, gh_g + (size_t)row * NN * 2 + kt * 128 + ch * 16);
        }
    };

    // prologue
#pragma unroll
    for (int it = 0; it < 8; it++) {
        int u = tid + it * 256;
        int row = u >> 4, ch = u & 15;
        cpa16(sb + SQH + row * 272 + ch * 16, Qh_g + row * 256 + ch * 16);
        cpa16(sb + SQL + row * 272 + ch * 16, Ql_g + row * 256 + ch * 16);
    }
    load_stage(0, 0);
    CP_COMMIT();
    load_stage(1, 1);
    CP_COMMIT();

    const int r0 = warp * 16 + (lane >> 2);
    float o[16][4];
#pragma unroll
    for (int d = 0; d < 16; d++)
#pragma unroll
        for (int c = 0; c < 4; c++) o[d][c] = 0.f;
    float l0 = 0.f, l1 = 0.f;

    const uint qoff = (uint)(warp * 16 + (lane & 15)) * 272 + ((lane >> 4) << 4);
    const uint koff = (uint)((lane & 7) + ((lane >> 4) << 3)) * 272 + (((lane >> 3) & 1) << 4);
    const uint goff = (uint)((lane & 7) + ((lane >> 4) << 3)) * 144 + (((lane >> 3) & 1) << 4);

    float accA[8][4], accB[8][4];

    // S into given accumulator from K stage s
    auto compute_S = [&](float (&acc)[8][4], int s) {
        const uint skh = sb + SKH(s);
        const uint skl = sb + SKL(s);
#pragma unroll
        for (int nt = 0; nt < 8; nt++)
#pragma unroll
            for (int c = 0; c < 4; c++) acc[nt][c] = 0.f;
#pragma unroll
        for (int kt = 0; kt < 8; kt++) {
            uint ah0, ah1, ah2, ah3, al0, al1, al2, al3;
            LDSM4(ah0, ah1, ah2, ah3, sb + SQH + qoff + kt * 32);
            LDSM4(al0, al1, al2, al3, sb + SQL + qoff + kt * 32);
#pragma unroll
            for (int np = 0; np < 4; np++) {
                uint bh0, bh1, bh2, bh3, bl0, bl1, bl2, bl3;
                LDSM4(bh0, bh1, bh2, bh3, skh + koff + (uint)np * 16 * 272 + kt * 32);
                LDSM4(bl0, bl1, bl2, bl3, skl + koff + (uint)np * 16 * 272 + kt * 32);
                mma_bf(acc[2*np][0], acc[2*np][1], acc[2*np][2], acc[2*np][3],
                       ah0, ah1, ah2, ah3, bh0, bh1);
                mma_bf(acc[2*np][0], acc[2*np][1], acc[2*np][2], acc[2*np][3],
                       ah0, ah1, ah2, ah3, bl0, bl1);
                mma_bf(acc[2*np][0], acc[2*np][1], acc[2*np][2], acc[2*np][3],
                       al0, al1, al2, al3, bh0, bh1);
                mma_bf(acc[2*np+1][0], acc[2*np+1][1], acc[2*np+1][2], acc[2*np+1][3],
                       ah0, ah1, ah2, ah3, bh2, bh3);
                mma_bf(acc[2*np+1][0], acc[2*np+1][1], acc[2*np+1][2], acc[2*np+1][3],
                       ah0, ah1, ah2, ah3, bl2, bl3);
                mma_bf(acc[2*np+1][0], acc[2*np+1][1], acc[2*np+1][2], acc[2*np+1][3],
                       al0, al1, al2, al3, bh2, bh3);
            }
        }
    };

    // one pipelined iteration: softmax(cur=S(t)), issue S(t+1) into nxt, PV(t)
    auto body = [&](float (&cur)[8][4], float (&nxt)[8][4], int t) {
        CP_WAIT0();            // stage (t+1) complete (committed one iteration ago)
        __syncthreads();       // all warps done with stage (t+2)%3's previous contents
        if (t + 2 < KTILES) load_stage(t + 2, (t + 2) % 3);
        CP_COMMIT();

        // softmax on cur (computed last iteration — latency fully hidden)
        uint ph[8][2];
#pragma unroll
        for (int nt = 0; nt < 8; nt++) {
            float p0 = __expf(cur[nt][0]);
            float p1 = __expf(cur[nt][1]);
            float p2 = __expf(cur[nt][2]);
            float p3 = __expf(cur[nt][3]);
            uint h01 = pack2(p0, p1);
            uint h23 = pack2(p2, p3);
            l0 += __uint_as_float(h01 << 16) + __uint_as_float(h01 & 0xffff0000u);
            l1 += __uint_as_float(h23 << 16) + __uint_as_float(h23 & 0xffff0000u);
            ph[nt][0] = h01; ph[nt][1] = h23;
        }

        // S(t+1): independent tensor work overlapping softmax/PV
        if (t + 1 < KTILES) compute_S(nxt, (t + 1) % 3);

        // PV(t): O += P_hi * G_hi
        const uint sgh = sb + SGH(t % 3);
#pragma unroll
        for (int kt2 = 0; kt2 < 4; kt2++) {
            uint ah0 = ph[2 * kt2][0], ah1 = ph[2 * kt2][1];
            uint ah2 = ph[2 * kt2 + 1][0], ah3 = ph[2 * kt2 + 1][1];
#pragma unroll
            for (int dp = 0; dp < 8; dp++) {
                uint g0, g1, g2, g3;
                LDSM4(g0, g1, g2, g3, sgh + goff + (uint)dp * 16 * 144 + kt2 * 32);
                mma_bf(o[2*dp][0], o[2*dp][1], o[2*dp][2], o[2*dp][3],
                       ah0, ah1, ah2, ah3, g0, g1);
                mma_bf(o[2*dp+1][0], o[2*dp+1][1], o[2*dp+1][2], o[2*dp+1][3],
                       ah0, ah1, ah2, ah3, g2, g3);
            }
        }
    };

    // wait Q + stages 0,1; compute S(0)
    CP_WAIT0();
    __syncthreads();
    compute_S(accA, 0);

    for (int t = 0; t < KTILES; t += 2) {
        body(accA, accB, t);
        body(accB, accA, t + 1);
    }

    // epilogue: quad-reduce l, normalize, emit Y bf16 hi/lo
    l0 += __shfl_xor_sync(0xffffffffu, l0, 1);
    l0 += __shfl_xor_sync(0xffffffffu, l0, 2);
    l1 += __shfl_xor_sync(0xffffffffu, l1, 1);
    l1 += __shfl_xor_sync(0xffffffffu, l1, 2);
    const float inv0 = 1.0f / l0, inv1 = 1.0f / l1;

    const uint row0 = (uint)(qt * 128 + r0);
    uint* yh = (uint*)g_Yh + (size_t)b * NN * (CI / 2);
    uint* yl = (uint*)g_Yl + (size_t)b * NN * (CI / 2);
#pragma unroll
    for (int dn = 0; dn < 16; dn++) {
        uint i0 = row0 * 64 + dn * 4 + (lane & 3);
        uint i1 = i0 + 8 * 64;
        float v0 = o[dn][0] * inv0, v1 = o[dn][1] * inv0;
        float v2 = o[dn][2] * inv1, v3 = o[dn][3] * inv1;
        uint h0 = pack2(v0, v1), h1 = pack2(v2, v3);
        float e0 = v0 - __uint_as_float(h0 << 16);
        float e1 = v1 - __uint_as_float(h0 & 0xffff0000u);
        float e2 = v2 - __uint_as_float(h1 << 16);
        float e3 = v3 - __uint_as_float(h1 & 0xffff0000u);
        yh[i0] = h0; yl[i0] = pack2(e0, e1);
        yh[i1] = h1; yl[i1] = pack2(e2, e3);
    }
}

// ---------------- kernel 3: mma wgemm (ldmatrix) ----------------
#define WG_YH 0
#define WG_YL 34816
#define WG_WH 69632
#define WG_WL 104448
#define WG_SMEM 139264

extern __shared__ char sm_w[];

__global__ void __launch_bounds__(256, 1) wgemm_kernel(const float* __restrict__ Wb)
{
    const int b  = blockIdx.z;
    const int oh = blockIdx.y;
    const int n0 = blockIdx.x * 128;
    const int tid = threadIdx.x;
    const int lane = tid & 31, warp = tid >> 5;
    const uint sb = smem_u32(sm_w);

    {
        const char* yh = (const char*)(g_Yh + (size_t)(b * NN + n0) * CI);
        const char* yl = (const char*)(g_Yl + (size_t)(b * NN + n0) * CI);
        const char* wh = (const char*)(g_Wwh + (size_t)(oh * 128) * CI);
        const char* wl = (const char*)(g_Wwl + (size_t)(oh * 128) * CI);
#pragma unroll
        for (int it = 0; it < 8; it++) {
            int u = tid + it * 256;
            int row = u >> 4, ch = u & 15;
            cpa16(sb + WG_YH + row * 272 + ch * 16, yh + (size_t)row * 256 + ch * 16);
            cpa16(sb + WG_YL + row * 272 + ch * 16, yl + (size_t)row * 256 + ch * 16);
            cpa16(sb + WG_WH + row * 272 + ch * 16, wh + (size_t)row * 256 + ch * 16);
            cpa16(sb + WG_WL + row * 272 + ch * 16, wl + (size_t)row * 256 + ch * 16);
        }
    }
    CP_COMMIT();
    CP_WAIT0();
    __syncthreads();

    const int r0 = warp * 16 + (lane >> 2);
    float acc[16][4];
#pragma unroll
    for (int i = 0; i < 16; i++)
#pragma unroll
        for (int c = 0; c < 4; c++) acc[i][c] = 0.f;

    const uint qoff = (uint)(warp * 16 + (lane & 15)) * 272 + ((lane >> 4) << 4);
    const uint koff = (uint)((lane & 7) + ((lane >> 4) << 3)) * 272 + (((lane >> 3) & 1) << 4);

#pragma unroll
    for (int kt = 0; kt < 8; kt++) {
        uint ah0, ah1, ah2, ah3, al0, al1, al2, al3;
        LDSM4(ah0, ah1, ah2, ah3, sb + WG_YH + qoff + kt * 32);
        LDSM4(al0, al1, al2, al3, sb + WG_YL + qoff + kt * 32);
#pragma unroll
        for (int op = 0; op < 8; op++) {
            uint bh0, bh1, bh2, bh3, bl0, bl1, bl2, bl3;
            LDSM4(bh0, bh1, bh2, bh3, sb + WG_WH + koff + (uint)op * 16 * 272 + kt * 32);
            LDSM4(bl0, bl1, bl2, bl3, sb + WG_WL + koff + (uint)op * 16 * 272 + kt * 32);
            mma_bf(acc[2*op][0], acc[2*op][1], acc[2*op][2], acc[2*op][3],
                   ah0, ah1, ah2, ah3, bh0, bh1);
            mma_bf(acc[2*op][0], acc[2*op][1], acc[2*op][2], acc[2*op][3],
                   ah0, ah1, ah2, ah3, bl0, bl1);
            mma_bf(acc[2*op][0], acc[2*op][1], acc[2*op][2], acc[2*op][3],
                   al0, al1, al2, al3, bh0, bh1);
            mma_bf(acc[2*op+1][0], acc[2*op+1][1], acc[2*op+1][2], acc[2*op+1][3],
                   ah0, ah1, ah2, ah3, bh2, bh3);
            mma_bf(acc[2*op+1][0], acc[2*op+1][1], acc[2*op+1][2], acc[2*op+1][3],
                   ah0, ah1, ah2, ah3, bl2, bl3);
            mma_bf(acc[2*op+1][0], acc[2*op+1][1], acc[2*op+1][2], acc[2*op+1][3],
                   al0, al1, al2, al3, bh2, bh3);
        }
    }

    float* wy = g_WY + (size_t)(b * NN + n0) * CC + oh * 128;
#pragma unroll
    for (int ot = 0; ot < 16; ot++) {
        int o = ot * 8 + (lane & 3) * 2;
        float b0 = Wb[oh * 128 + o], b1 = Wb[oh * 128 + o + 1];
        *(float2*)(wy + (size_t)r0 * CC + o) = make_float2(acc[ot][0] + b0, acc[ot][1] + b1);
        *(float2*)(wy + (size_t)(r0 + 8) * CC + o) = make_float2(acc[ot][2] + b0, acc[ot][3] + b1);
    }
}

// ---------------- kernel 4a/4b: deterministic BN stats ----------------
__global__ void __launch_bounds__(256) stats1_kernel()
{
    const int blk = blockIdx.x;
    const int t = threadIdx.x;
    float s = 0.f, q = 0.f;
    const float* base = g_WY + (size_t)blk * 128 * CC + t;
    for (int r = 0; r < 128; r++) {
        float v = base[(size_t)r * CC];
        s += v; q += v * v;
    }
    g_psum[blk * CC + t] = s;
    g_psq [blk * CC + t] = q;
}
__global__ void __launch_bounds__(256) stats2_kernel()
{
    const int t = threadIdx.x;
    float s = 0.f, q = 0.f;
    for (int p = 0; p < 128; p++) {
        s += g_psum[p * CC + t];
        q += g_psq [p * CC + t];
    }
    const float invn = 1.0f / (float)(BB * NN);
    float mean = s * invn;
    float var  = q * invn - mean * mean;
    g_mean[t] = mean;
    g_rstd[t] = rsqrtf(var + BN_EPS);
}

// ---------------- kernel 5: BN apply + scale + residual (with transpose) ----------------
__global__ void __launch_bounds__(256) apply_kernel(
    const float* __restrict__ x,
    const float* __restrict__ gamma, const float* __restrict__ beta,
    const float* __restrict__ scale, float* __restrict__ out)
{
    __shared__ float st[64 * 65];
    const int n0 = blockIdx.x * 64;
    const int c0 = blockIdx.y * 64;
    const int b  = blockIdx.z;
    const int tid = threadIdx.x;
    const float s = scale[0];

#pragma unroll
    for (int r = 0; r < 16; r++) {
        int idx = tid + r * 256;
        int nl = idx >> 6, cc = idx & 63;
        st[cc * 65 + nl] = g_WY[((size_t)(b * NN + n0 + nl)) * CC + c0 + cc];
    }
    __syncthreads();
#pragma unroll
    for (int r = 0; r < 16; r++) {
        int idx = tid + r * 256;
        int cc = idx >> 6, nl = idx & 63;
        int c = c0 + cc;
        float wv = st[cc * 65 + nl];
        float v = s * ((wv - g_mean[c]) * g_rstd[c] * gamma[c] + beta[c])
                + x[((size_t)(b * CC + c)) * NN + n0 + nl];
        out[((size_t)(b * CC + c)) * NN + n0 + nl] = v;
    }
}

// ---------------- launcher ----------------
extern "C" void kernel_launch(void* const* d_in, const int* in_sizes, int n_in,
                              void* d_out, int out_size)
{
    const float* x     = (const float*)d_in[0];
    const float* gw    = (const float*)d_in[1];
    const float* gb    = (const float*)d_in[2];
    const float* tw    = (const float*)d_in[3];
    const float* tb    = (const float*)d_in[4];
    const float* pw    = (const float*)d_in[5];
    const float* pb    = (const float*)d_in[6];
    const float* Ww    = (const float*)d_in[7];
    const float* Wb    = (const float*)d_in[8];
    const float* gamma = (const float*)d_in[9];
    const float* beta  = (const float*)d_in[10];
    const float* scale = (const float*)d_in[11];
    float* out = (float*)d_out;

    cudaFuncSetAttribute(proj_kernel,
                         cudaFuncAttributeMaxDynamicSharedMemorySize, PROJ_SMEM);
    cudaFuncSetAttribute(attn_kernel,
                         cudaFuncAttributeMaxDynamicSharedMemorySize, ATTN_SMEM);
    cudaFuncSetAttribute(wgemm_kernel,
                         cudaFuncAttributeMaxDynamicSharedMemorySize, WG_SMEM);

    xcvt_kernel<<<dim3(NN / 64, CC / 64, BB), 256>>>(x);
    wcvt_kernel<<<64, 256>>>(gw, tw, pw, Ww);
    proj_kernel<<<dim3(NN / 128, BB, 3), 256, PROJ_SMEM>>>(gb, tb, pb);
    attn_kernel<<<dim3(NN / 128, BB), 256, ATTN_SMEM>>>();
    wgemm_kernel<<<dim3(NN / 128, 2, BB), 256, WG_SMEM>>>(Wb);
    stats1_kernel<<<128, 256>>>();
    stats2_kernel<<<1, 256>>>();
    apply_kernel<<<dim3(NN / 64, CC / 64, BB), 256>>>(x, gamma, beta, scale, out);
}

// round 13
// speedup vs baseline: 1.1415x; 1.1415x over previous
#include <cuda_runtime.h>

#define BB 4
#define CC 256
#define CI 128
#define NN 4096
#define BN_EPS 1e-5f

typedef unsigned int uint;
typedef unsigned short ushort;

// ---------------- scratch (no allocations allowed) ----------------
__device__ __align__(16) ushort g_Xh[BB * NN * CC];   // x^T hi [b][n][c]
__device__ __align__(16) ushort g_Xl[BB * NN * CC];
__device__ __align__(16) ushort g_PWh[3 * CI * CC];   // proj weights hi (g, theta, phi) [which][o][c]
__device__ __align__(16) ushort g_PWl[3 * CI * CC];
__device__ __align__(16) ushort g_Wwh[CC * CI];       // W conv weight hi [o][d]
__device__ __align__(16) ushort g_Wwl[CC * CI];
__device__ __align__(16) ushort g_Qh[BB * NN * CI];   // theta hi  [b][n][d]  (hi only)
__device__ __align__(16) ushort g_Kh[BB * NN * CI];   // phi hi    [b][m][d]
__device__ __align__(16) ushort g_Kl[BB * NN * CI];
__device__ __align__(16) ushort g_Gth[BB * CI * NN];  // g^T hi    [b][d][m]
__device__ __align__(16) ushort g_Yh[BB * NN * CI];   // attention out hi [b][n][d]
__device__ __align__(16) ushort g_Yl[BB * NN * CI];
__device__ __align__(16) float g_WY[BB * NN * CC];    // W conv out [b][n][o]
__device__ __align__(16) float g_psum[128 * CC];
__device__ __align__(16) float g_psq [128 * CC];
__device__ float g_mean[CC];
__device__ float g_rstd[CC];

// ---------------- helpers ----------------
__device__ __forceinline__ ushort bf16rn(float v) {
    uint u = __float_as_uint(v);
    return (ushort)((u + 0x7FFFu + ((u >> 16) & 1u)) >> 16);
}
__device__ __forceinline__ uint smem_u32(const void* p) {
    uint a;
    asm("{ .reg .u64 t; cvta.to.shared.u64 t, %1; cvt.u32.u64 %0, t; }" : "=r"(a) : "l"(p));
    return a;
}
__device__ __forceinline__ void cpa16(uint s, const void* g) {
    asm volatile("cp.async.cg.shared.global [%0], [%1], 16;" :: "r"(s), "l"(g) : "memory");
}
#define CP_COMMIT() asm volatile("cp.async.commit_group;" ::: "memory")
#define CP_WAIT0()  asm volatile("cp.async.wait_group 0;" ::: "memory")
#define CP_WAIT1()  asm volatile("cp.async.wait_group 1;" ::: "memory")

#define LDSM4(r0, r1, r2, r3, addr) \
    asm volatile("ldmatrix.sync.aligned.m8n8.x4.shared.b16 {%0,%1,%2,%3}, [%4];" \
        : "=r"(r0), "=r"(r1), "=r"(r2), "=r"(r3) : "r"(addr))

// pack2(lo, hi): bf16x2 with lo in low half
__device__ __forceinline__ uint pack2(float lo, float hi) {
    uint r;
    asm("cvt.rn.bf16x2.f32 %0, %1, %2;" : "=r"(r) : "f"(hi), "f"(lo));
    return r;
}
__device__ __forceinline__ void mma_bf(float& d0, float& d1, float& d2, float& d3,
                                       uint a0, uint a1, uint a2, uint a3,
                                       uint b0, uint b1) {
    asm volatile("mma.sync.aligned.m16n8k16.row.col.f32.bf16.bf16.f32 "
        "{%0,%1,%2,%3},{%4,%5,%6,%7},{%8,%9},{%0,%1,%2,%3};"
        : "+f"(d0), "+f"(d1), "+f"(d2), "+f"(d3)
        : "r"(a0), "r"(a1), "r"(a2), "r"(a3), "r"(b0), "r"(b1));
}

// ---------------- kernel 0a: transpose + split x -> bf16 hi/lo [b][n][c] ----------------
__global__ void __launch_bounds__(256) xcvt_kernel(const float* __restrict__ x)
{
    __shared__ float st[64 * 65];
    const int n0 = blockIdx.x * 64;
    const int c0 = blockIdx.y * 64;
    const int b  = blockIdx.z;
    const int tid = threadIdx.x;
#pragma unroll
    for (int r = 0; r < 16; r++) {
        int idx = tid + r * 256;
        int cc = idx >> 6, nl = idx & 63;
        st[nl * 65 + cc] = x[((size_t)(b * CC + c0 + cc)) * NN + n0 + nl];
    }
    __syncthreads();
#pragma unroll
    for (int r = 0; r < 16; r++) {
        int idx = tid + r * 256;
        int nl = idx >> 6, cc = idx & 63;
        float v = st[nl * 65 + cc];
        ushort h = bf16rn(v);
        ushort l = bf16rn(v - __uint_as_float(((uint)h) << 16));
        size_t o = ((size_t)(b * NN + n0 + nl)) * CC + c0 + cc;
        g_Xh[o] = h;
        g_Xl[o] = l;
    }
}

// ---------------- kernel 0b: split weights -> bf16 hi/lo ----------------
__global__ void __launch_bounds__(256) wcvt_kernel(
    const float* __restrict__ gw, const float* __restrict__ tw,
    const float* __restrict__ pw, const float* __restrict__ Ww)
{
    const int total = 3 * CI * CC + CC * CI;
    for (int idx = blockIdx.x * 256 + threadIdx.x; idx < total; idx += gridDim.x * 256) {
        float v;
        if (idx < 3 * CI * CC) {
            int which = idx / (CI * CC), r = idx % (CI * CC);
            v = (which == 0 ? gw : which == 1 ? tw : pw)[r];
            ushort h = bf16rn(v);
            g_PWh[idx] = h;
            g_PWl[idx] = bf16rn(v - __uint_as_float(((uint)h) << 16));
        } else {
            int r = idx - 3 * CI * CC;
            v = Ww[r];
            ushort h = bf16rn(v);
            g_Wwh[r] = h;
            g_Wwl[r] = bf16rn(v - __uint_as_float(((uint)h) << 16));
        }
    }
}

// ---------------- kernel 1: mma projections ----------------
#define PJ_XH(buf) ((buf) * 73728)
#define PJ_XL(buf) ((buf) * 73728 + 18432)
#define PJ_WH(buf) ((buf) * 73728 + 36864)
#define PJ_WL(buf) ((buf) * 73728 + 55296)
#define PROJ_SMEM (2 * 73728)

extern __shared__ char sm_p[];

__global__ void __launch_bounds__(256, 1) proj_kernel(
    const float* __restrict__ gb_, const float* __restrict__ tb_,
    const float* __restrict__ pb_)
{
    const int b  = blockIdx.y;
    const int n0 = blockIdx.x * 128;
    const int which = blockIdx.z;              // 0=g->Gt(hi only), 1=theta->Q(hi only), 2=phi->K(hi+lo)
    const int tid = threadIdx.x;
    const int lane = tid & 31, warp = tid >> 5;
    const uint sb = smem_u32(sm_p);
    const float* bias = (which == 0) ? gb_ : (which == 1) ? tb_ : pb_;

    const char* Xh_g = (const char*)(g_Xh + (size_t)(b * NN + n0) * CC);
    const char* Xl_g = (const char*)(g_Xl + (size_t)(b * NN + n0) * CC);
    const char* Wh_g = (const char*)(g_PWh + which * CI * CC);
    const char* Wl_g = (const char*)(g_PWl + which * CI * CC);

    auto load_chunk = [&](int ch) {
        if (ch < 4) {
            int buf = ch & 1;
            int cb = ch * 128;
#pragma unroll
            for (int it = 0; it < 4; it++) {
                int u = tid + it * 256;
                int row = u >> 3, seg = u & 7;
                cpa16(sb + PJ_XH(buf) + row * 144 + seg * 16, Xh_g + (size_t)row * 512 + cb + seg * 16);
                cpa16(sb + PJ_XL(buf) + row * 144 + seg * 16, Xl_g + (size_t)row * 512 + cb + seg * 16);
                cpa16(sb + PJ_WH(buf) + row * 144 + seg * 16, Wh_g + (size_t)row * 512 + cb + seg * 16);
                cpa16(sb + PJ_WL(buf) + row * 144 + seg * 16, Wl_g + (size_t)row * 512 + cb + seg * 16);
            }
        }
        CP_COMMIT();
    };

    load_chunk(0);
    load_chunk(1);

    const int r0 = warp * 16 + (lane >> 2);
    float acc[16][4];
#pragma unroll
    for (int i = 0; i < 16; i++)
#pragma unroll
        for (int c = 0; c < 4; c++) acc[i][c] = 0.f;

    const uint qoff144 = (uint)(warp * 16 + (lane & 15)) * 144 + ((lane >> 4) << 4);
    const uint koff144 = (uint)((lane & 7) + ((lane >> 4) << 3)) * 144 + (((lane >> 3) & 1) << 4);

    for (int ch = 0; ch < 4; ch++) {
        CP_WAIT1();
        __syncthreads();
        int buf = ch & 1;
#pragma unroll
        for (int kt = 0; kt < 4; kt++) {
            uint ah0, ah1, ah2, ah3, al0, al1, al2, al3;
            LDSM4(ah0, ah1, ah2, ah3, sb + PJ_XH(buf) + qoff144 + kt * 32);
            LDSM4(al0, al1, al2, al3, sb + PJ_XL(buf) + qoff144 + kt * 32);
#pragma unroll
            for (int op = 0; op < 8; op++) {
                uint bh0, bh1, bh2, bh3, bl0, bl1, bl2, bl3;
                LDSM4(bh0, bh1, bh2, bh3, sb + PJ_WH(buf) + koff144 + (uint)op * 16 * 144 + kt * 32);
                LDSM4(bl0, bl1, bl2, bl3, sb + PJ_WL(buf) + koff144 + (uint)op * 16 * 144 + kt * 32);
                mma_bf(acc[2*op][0], acc[2*op][1], acc[2*op][2], acc[2*op][3],
                       ah0, ah1, ah2, ah3, bh0, bh1);
                mma_bf(acc[2*op][0], acc[2*op][1], acc[2*op][2], acc[2*op][3],
                       ah0, ah1, ah2, ah3, bl0, bl1);
                mma_bf(acc[2*op][0], acc[2*op][1], acc[2*op][2], acc[2*op][3],
                       al0, al1, al2, al3, bh0, bh1);
                mma_bf(acc[2*op+1][0], acc[2*op+1][1], acc[2*op+1][2], acc[2*op+1][3],
                       ah0, ah1, ah2, ah3, bh2, bh3);
                mma_bf(acc[2*op+1][0], acc[2*op+1][1], acc[2*op+1][2], acc[2*op+1][3],
                       ah0, ah1, ah2, ah3, bl2, bl3);
                mma_bf(acc[2*op+1][0], acc[2*op+1][1], acc[2*op+1][2], acc[2*op+1][3],
                       al0, al1, al2, al3, bh2, bh3);
            }
        }
        __syncthreads();
        load_chunk(ch + 2);
    }
    CP_WAIT0();

#pragma unroll
    for (int ot = 0; ot < 16; ot++) {
        int o = ot * 8 + (lane & 3) * 2;
        float b0 = bias[o], b1 = bias[o + 1];
        acc[ot][0] += b0; acc[ot][1] += b1;
        acc[ot][2] += b0; acc[ot][3] += b1;
    }

    if (which == 2) {
        // phi: write hi + lo
        uint* dh = (uint*)g_Kh + (size_t)(b * NN + n0) * (CI / 2);
        uint* dl = (uint*)g_Kl + (size_t)(b * NN + n0) * (CI / 2);
#pragma unroll
        for (int ot = 0; ot < 16; ot++) {
            uint i0 = (uint)r0 * 64 + ot * 4 + (lane & 3);
            uint i1 = i0 + 8 * 64;
            uint h0 = pack2(acc[ot][0], acc[ot][1]);
            uint h1 = pack2(acc[ot][2], acc[ot][3]);
            float e0 = acc[ot][0] - __uint_as_float(h0 << 16);
            float e1 = acc[ot][1] - __uint_as_float(h0 & 0xffff0000u);
            float e2 = acc[ot][2] - __uint_as_float(h1 << 16);
            float e3 = acc[ot][3] - __uint_as_float(h1 & 0xffff0000u);
            dh[i0] = h0; dl[i0] = pack2(e0, e1);
            dh[i1] = h1; dl[i1] = pack2(e2, e3);
        }
    } else if (which == 1) {
        // theta: hi only
        uint* dh = (uint*)g_Qh + (size_t)(b * NN + n0) * (CI / 2);
#pragma unroll
        for (int ot = 0; ot < 16; ot++) {
            uint i0 = (uint)r0 * 64 + ot * 4 + (lane & 3);
            uint i1 = i0 + 8 * 64;
            dh[i0] = pack2(acc[ot][0], acc[ot][1]);
            dh[i1] = pack2(acc[ot][2], acc[ot][3]);
        }
    } else {
        // g: hi-only transpose through smem
        ushort* st = (ushort*)sm_p;
        __syncthreads();
#pragma unroll
        for (int ot = 0; ot < 16; ot++) {
            int o = ot * 8 + (lane & 3) * 2;
#pragma unroll
            for (int c = 0; c < 4; c++) {
                int oo = o + (c & 1);
                int rr = (c < 2) ? r0 : (r0 + 8);
                st[oo * 136 + rr] = bf16rn(acc[ot][c]);
            }
        }
        __syncthreads();
#pragma unroll
        for (int it = 0; it < 8; it++) {
            int u = tid + it * 256;
            int o = u >> 4, seg = u & 15;
            *(uint4*)((char*)g_Gth + (((size_t)(b * CI + o)) * NN + n0) * 2 + seg * 16)
                = *(const uint4*)((const char*)st + o * 272 + seg * 16);
        }
    }
}

// ---------------- kernel 2: flash attention (ldmatrix, 3-stage, Q hi-only) ----------------
#define SQH 0
#define SKH(s) (34816 + (s) * 34816)
#define SKL(s) (34816 + (s) * 34816 + 17408)
#define SGH(s) (139264 + (s) * 18432)
#define ATTN_SMEM 194560
#define KTILES 64

extern __shared__ char sm_a[];

__global__ void __launch_bounds__(256, 1) attn_kernel()
{
    const int b  = blockIdx.y;
    const int qt = blockIdx.x;
    const int tid = threadIdx.x;
    const int lane = tid & 31, warp = tid >> 5;
    const uint sb = smem_u32(sm_a);

    const size_t qbase = (size_t)(b * NN + qt * 128) * CI;
    const char* Qh_g = (const char*)(g_Qh + qbase);
    const char* gh_g = (const char*)(g_Gth + (size_t)(b * CI) * NN);

    auto load_stage = [&](int kt, int s) {
        const char* khs = (const char*)(g_Kh + (size_t)(b * NN + kt * 64) * CI);
        const char* kls = (const char*)(g_Kl + (size_t)(b * NN + kt * 64) * CI);
#pragma unroll
        for (int it = 0; it < 4; it++) {
            int u = tid + it * 256;
            int row = u >> 4, ch = u & 15;
            cpa16(sb + SKH(s) + row * 272 + ch * 16, khs + row * 256 + ch * 16);
            cpa16(sb + SKL(s) + row * 272 + ch * 16, kls + row * 256 + ch * 16);
        }
#pragma unroll
        for (int it = 0; it < 4; it++) {
            int u = tid + it * 256;
            int row = u >> 3, ch = u & 7;
            cpa16(sb + SGH(s) + row * 144 + ch * 16, gh_g + (size_t)row * NN * 2 + kt * 128 + ch * 16);
        }
    };

    // prologue: Q + stage0 in group0, stage1 in group1
#pragma unroll
    for (int it = 0; it < 4; it++) {
        int u = tid + it * 256;
        int row = u >> 3, ch = u & 7;
        cpa16(sb + SQH + row * 272 + ch * 32 + ((row & 1) << 4),
              Qh_g + row * 256 + ch * 32 + ((row & 1) << 4));
        cpa16(sb + SQH + row * 272 + ch * 32 + (((row & 1) ^ 1) << 4),
              Qh_g + row * 256 + ch * 32 + (((row & 1) ^ 1) << 4));
    }
    load_stage(0, 0);
    CP_COMMIT();
    load_stage(1, 1);
    CP_COMMIT();

    const int r0 = warp * 16 + (lane >> 2);
    float o[16][4];
#pragma unroll
    for (int d = 0; d < 16; d++)
#pragma unroll
        for (int c = 0; c < 4; c++) o[d][c] = 0.f;
    float l0 = 0.f, l1 = 0.f;

    const uint qoff = (uint)(warp * 16 + (lane & 15)) * 272 + ((lane >> 4) << 4);
    const uint koff = (uint)((lane & 7) + ((lane >> 4) << 3)) * 272 + (((lane >> 3) & 1) << 4);
    const uint goff = (uint)((lane & 7) + ((lane >> 4) << 3)) * 144 + (((lane >> 3) & 1) << 4);

    int stage = 0;
    for (int t = 0; t < KTILES; t++) {
        CP_WAIT1();
        __syncthreads();
        int pst = stage + 2 >= 3 ? stage - 1 : stage + 2;
        if (t + 2 < KTILES) load_stage(t + 2, pst);
        CP_COMMIT();

        const uint skh = sb + SKH(stage);
        const uint skl = sb + SKL(stage);
        const uint sgh = sb + SGH(stage);

        float acc[8][4];
#pragma unroll
        for (int nt = 0; nt < 8; nt++)
#pragma unroll
            for (int c = 0; c < 4; c++) acc[nt][c] = 0.f;

        // S = Q_hi * (K_hi + K_lo)   (Q_lo term dropped; consistent-weights mechanism)
#pragma unroll
        for (int kt = 0; kt < 8; kt++) {
            uint ah0, ah1, ah2, ah3;
            LDSM4(ah0, ah1, ah2, ah3, sb + SQH + qoff + kt * 32);
#pragma unroll
            for (int np = 0; np < 4; np++) {
                uint bh0, bh1, bh2, bh3, bl0, bl1, bl2, bl3;
                LDSM4(bh0, bh1, bh2, bh3, skh + koff + (uint)np * 16 * 272 + kt * 32);
                LDSM4(bl0, bl1, bl2, bl3, skl + koff + (uint)np * 16 * 272 + kt * 32);
                mma_bf(acc[2*np][0], acc[2*np][1], acc[2*np][2], acc[2*np][3],
                       ah0, ah1, ah2, ah3, bh0, bh1);
                mma_bf(acc[2*np][0], acc[2*np][1], acc[2*np][2], acc[2*np][3],
                       ah0, ah1, ah2, ah3, bl0, bl1);
                mma_bf(acc[2*np+1][0], acc[2*np+1][1], acc[2*np+1][2], acc[2*np+1][3],
                       ah0, ah1, ah2, ah3, bh2, bh3);
                mma_bf(acc[2*np+1][0], acc[2*np+1][1], acc[2*np+1][2], acc[2*np+1][3],
                       ah0, ah1, ah2, ah3, bl2, bl3);
            }
        }

        // softmax: exp, round to bf16; l sums the ROUNDED values (consistency)
        uint ph[8][2];
#pragma unroll
        for (int nt = 0; nt < 8; nt++) {
            float p0 = __expf(acc[nt][0]);
            float p1 = __expf(acc[nt][1]);
            float p2 = __expf(acc[nt][2]);
            float p3 = __expf(acc[nt][3]);
            uint h01 = pack2(p0, p1);
            uint h23 = pack2(p2, p3);
            l0 += __uint_as_float(h01 << 16) + __uint_as_float(h01 & 0xffff0000u);
            l1 += __uint_as_float(h23 << 16) + __uint_as_float(h23 & 0xffff0000u);
            ph[nt][0] = h01; ph[nt][1] = h23;
        }

        // O += P_hi * G_hi
#pragma unroll
        for (int kt2 = 0; kt2 < 4; kt2++) {
            uint ah0 = ph[2 * kt2][0], ah1 = ph[2 * kt2][1];
            uint ah2 = ph[2 * kt2 + 1][0], ah3 = ph[2 * kt2 + 1][1];
#pragma unroll
            for (int dp = 0; dp < 8; dp++) {
                uint g0, g1, g2, g3;
                LDSM4(g0, g1, g2, g3, sgh + goff + (uint)dp * 16 * 144 + kt2 * 32);
                mma_bf(o[2*dp][0], o[2*dp][1], o[2*dp][2], o[2*dp][3],
                       ah0, ah1, ah2, ah3, g0, g1);
                mma_bf(o[2*dp+1][0], o[2*dp+1][1], o[2*dp+1][2], o[2*dp+1][3],
                       ah0, ah1, ah2, ah3, g2, g3);
            }
        }

        stage = (stage + 1 == 3) ? 0 : stage + 1;
    }

    // epilogue: quad-reduce l, normalize, emit Y bf16 hi/lo
    l0 += __shfl_xor_sync(0xffffffffu, l0, 1);
    l0 += __shfl_xor_sync(0xffffffffu, l0, 2);
    l1 += __shfl_xor_sync(0xffffffffu, l1, 1);
    l1 += __shfl_xor_sync(0xffffffffu, l1, 2);
    const float inv0 = 1.0f / l0, inv1 = 1.0f / l1;

    const uint row0 = (uint)(qt * 128 + r0);
    uint* yh = (uint*)g_Yh + (size_t)b * NN * (CI / 2);
    uint* yl = (uint*)g_Yl + (size_t)b * NN * (CI / 2);
#pragma unroll
    for (int dn = 0; dn < 16; dn++) {
        uint i0 = row0 * 64 + dn * 4 + (lane & 3);
        uint i1 = i0 + 8 * 64;
        float v0 = o[dn][0] * inv0, v1 = o[dn][1] * inv0;
        float v2 = o[dn][2] * inv1, v3 = o[dn][3] * inv1;
        uint h0 = pack2(v0, v1), h1 = pack2(v2, v3);
        float e0 = v0 - __uint_as_float(h0 << 16);
        float e1 = v1 - __uint_as_float(h0 & 0xffff0000u);
        float e2 = v2 - __uint_as_float(h1 << 16);
        float e3 = v3 - __uint_as_float(h1 & 0xffff0000u);
        yh[i0] = h0; yl[i0] = pack2(e0, e1);
        yh[i1] = h1; yl[i1] = pack2(e2, e3);
    }
}

// ---------------- kernel 3: mma wgemm (ldmatrix) ----------------
#define WG_YH 0
#define WG_YL 34816
#define WG_WH 69632
#define WG_WL 104448
#define WG_SMEM 139264

extern __shared__ char sm_w[];

__global__ void __launch_bounds__(256, 1) wgemm_kernel(const float* __restrict__ Wb)
{
    const int b  = blockIdx.z;
    const int oh = blockIdx.y;
    const int n0 = blockIdx.x * 128;
    const int tid = threadIdx.x;
    const int lane = tid & 31, warp = tid >> 5;
    const uint sb = smem_u32(sm_w);

    {
        const char* yh = (const char*)(g_Yh + (size_t)(b * NN + n0) * CI);
        const char* yl = (const char*)(g_Yl + (size_t)(b * NN + n0) * CI);
        const char* wh = (const char*)(g_Wwh + (size_t)(oh * 128) * CI);
        const char* wl = (const char*)(g_Wwl + (size_t)(oh * 128) * CI);
#pragma unroll
        for (int it = 0; it < 8; it++) {
            int u = tid + it * 256;
            int row = u >> 4, ch = u & 15;
            cpa16(sb + WG_YH + row * 272 + ch * 16, yh + (size_t)row * 256 + ch * 16);
            cpa16(sb + WG_YL + row * 272 + ch * 16, yl + (size_t)row * 256 + ch * 16);
            cpa16(sb + WG_WH + row * 272 + ch * 16, wh + (size_t)row * 256 + ch * 16);
            cpa16(sb + WG_WL + row * 272 + ch * 16, wl + (size_t)row * 256 + ch * 16);
        }
    }
    CP_COMMIT();
    CP_WAIT0();
    __syncthreads();

    const int r0 = warp * 16 + (lane >> 2);
    float acc[16][4];
#pragma unroll
    for (int i = 0; i < 16; i++)
#pragma unroll
        for (int c = 0; c < 4; c++) acc[i][c] = 0.f;

    const uint qoff = (uint)(warp * 16 + (lane & 15)) * 272 + ((lane >> 4) << 4);
    const uint koff = (uint)((lane & 7) + ((lane >> 4) << 3)) * 272 + (((lane >> 3) & 1) << 4);

#pragma unroll
    for (int kt = 0; kt < 8; kt++) {
        uint ah0, ah1, ah2, ah3, al0, al1, al2, al3;
        LDSM4(ah0, ah1, ah2, ah3, sb + WG_YH + qoff + kt * 32);
        LDSM4(al0, al1, al2, al3, sb + WG_YL + qoff + kt * 32);
#pragma unroll
        for (int op = 0; op < 8; op++) {
            uint bh0, bh1, bh2, bh3, bl0, bl1, bl2, bl3;
            LDSM4(bh0, bh1, bh2, bh3, sb + WG_WH + koff + (uint)op * 16 * 272 + kt * 32);
            LDSM4(bl0, bl1, bl2, bl3, sb + WG_WL + koff + (uint)op * 16 * 272 + kt * 32);
            mma_bf(acc[2*op][0], acc[2*op][1], acc[2*op][2], acc[2*op][3],
                   ah0, ah1, ah2, ah3, bh0, bh1);
            mma_bf(acc[2*op][0], acc[2*op][1], acc[2*op][2], acc[2*op][3],
                   ah0, ah1, ah2, ah3, bl0, bl1);
            mma_bf(acc[2*op][0], acc[2*op][1], acc[2*op][2], acc[2*op][3],
                   al0, al1, al2, al3, bh0, bh1);
            mma_bf(acc[2*op+1][0], acc[2*op+1][1], acc[2*op+1][2], acc[2*op+1][3],
                   ah0, ah1, ah2, ah3, bh2, bh3);
            mma_bf(acc[2*op+1][0], acc[2*op+1][1], acc[2*op+1][2], acc[2*op+1][3],
                   ah0, ah1, ah2, ah3, bl2, bl3);
            mma_bf(acc[2*op+1][0], acc[2*op+1][1], acc[2*op+1][2], acc[2*op+1][3],
                   al0, al1, al2, al3, bh2, bh3);
        }
    }

    float* wy = g_WY + (size_t)(b * NN + n0) * CC + oh * 128;
#pragma unroll
    for (int ot = 0; ot < 16; ot++) {
        int o = ot * 8 + (lane & 3) * 2;
        float b0 = Wb[oh * 128 + o], b1 = Wb[oh * 128 + o + 1];
        *(float2*)(wy + (size_t)r0 * CC + o) = make_float2(acc[ot][0] + b0, acc[ot][1] + b1);
        *(float2*)(wy + (size_t)(r0 + 8) * CC + o) = make_float2(acc[ot][2] + b0, acc[ot][3] + b1);
    }
}

// ---------------- kernel 4a/4b: deterministic BN stats ----------------
__global__ void __launch_bounds__(256) stats1_kernel()
{
    const int blk = blockIdx.x;
    const int t = threadIdx.x;
    float s = 0.f, q = 0.f;
    const float* base = g_WY + (size_t)blk * 128 * CC + t;
    for (int r = 0; r < 128; r++) {
        float v = base[(size_t)r * CC];
        s += v; q += v * v;
    }
    g_psum[blk * CC + t] = s;
    g_psq [blk * CC + t] = q;
}
__global__ void __launch_bounds__(256) stats2_kernel()
{
    const int t = threadIdx.x;
    float s = 0.f, q = 0.f;
    for (int p = 0; p < 128; p++) {
        s += g_psum[p * CC + t];
        q += g_psq [p * CC + t];
    }
    const float invn = 1.0f / (float)(BB * NN);
    float mean = s * invn;
    float var  = q * invn - mean * mean;
    g_mean[t] = mean;
    g_rstd[t] = rsqrtf(var + BN_EPS);
}

// ---------------- kernel 5: BN apply + scale + residual (with transpose) ----------------
__global__ void __launch_bounds__(256) apply_kernel(
    const float* __restrict__ x,
    const float* __restrict__ gamma, const float* __restrict__ beta,
    const float* __restrict__ scale, float* __restrict__ out)
{
    __shared__ float st[64 * 65];
    const int n0 = blockIdx.x * 64;
    const int c0 = blockIdx.y * 64;
    const int b  = blockIdx.z;
    const int tid = threadIdx.x;
    const float s = scale[0];

#pragma unroll
    for (int r = 0; r < 16; r++) {
        int idx = tid + r * 256;
        int nl = idx >> 6, cc = idx & 63;
        st[cc * 65 + nl] = g_WY[((size_t)(b * NN + n0 + nl)) * CC + c0 + cc];
    }
    __syncthreads();
#pragma unroll
    for (int r = 0; r < 16; r++) {
        int idx = tid + r * 256;
        int cc = idx >> 6, nl = idx & 63;
        int c = c0 + cc;
        float wv = st[cc * 65 + nl];
        float v = s * ((wv - g_mean[c]) * g_rstd[c] * gamma[c] + beta[c])
                + x[((size_t)(b * CC + c)) * NN + n0 + nl];
        out[((size_t)(b * CC + c)) * NN + n0 + nl] = v;
    }
}

// ---------------- launcher ----------------
extern "C" void kernel_launch(void* const* d_in, const int* in_sizes, int n_in,
                              void* d_out, int out_size)
{
    const float* x     = (const float*)d_in[0];
    const float* gw    = (const float*)d_in[1];
    const float* gb    = (const float*)d_in[2];
    const float* tw    = (const float*)d_in[3];
    const float* tb    = (const float*)d_in[4];
    const float* pw    = (const float*)d_in[5];
    const float* pb    = (const float*)d_in[6];
    const float* Ww    = (const float*)d_in[7];
    const float* Wb    = (const float*)d_in[8];
    const float* gamma = (const float*)d_in[9];
    const float* beta  = (const float*)d_in[10];
    const float* scale = (const float*)d_in[11];
    float* out = (float*)d_out;

    cudaFuncSetAttribute(proj_kernel,
                         cudaFuncAttributeMaxDynamicSharedMemorySize, PROJ_SMEM);
    cudaFuncSetAttribute(attn_kernel,
                         cudaFuncAttributeMaxDynamicSharedMemorySize, ATTN_SMEM);
    cudaFuncSetAttribute(wgemm_kernel,
                         cudaFuncAttributeMaxDynamicSharedMemorySize, WG_SMEM);

    xcvt_kernel<<<dim3(NN / 64, CC / 64, BB), 256>>>(x);
    wcvt_kernel<<<64, 256>>>(gw, tw, pw, Ww);
    proj_kernel<<<dim3(NN / 128, BB, 3), 256, PROJ_SMEM>>>(gb, tb, pb);
    attn_kernel<<<dim3(NN / 128, BB), 256, ATTN_SMEM>>>();
    wgemm_kernel<<<dim3(NN / 128, 2, BB), 256, WG_SMEM>>>(Wb);
    stats1_kernel<<<128, 256>>>();
    stats2_kernel<<<1, 256>>>();
    apply_kernel<<<dim3(NN / 64, CC / 64, BB), 256>>>(x, gamma, beta, scale, out);
}

// round 14
// speedup vs baseline: 1.4011x; 1.2274x over previous
#include <cuda_runtime.h>

#define BB 4
#define CC 256
#define CI 128
#define NN 4096
#define BN_EPS 1e-5f

typedef unsigned int uint;
typedef unsigned short ushort;

// ---------------- scratch (no allocations allowed) ----------------
__device__ __align__(16) ushort g_Xh[BB * NN * CC];   // x^T hi [b][n][c]
__device__ __align__(16) ushort g_Xl[BB * NN * CC];
__device__ __align__(16) ushort g_PWh[3 * CI * CC];   // proj weights hi (g, theta, phi) [which][o][c]
__device__ __align__(16) ushort g_PWl[3 * CI * CC];
__device__ __align__(16) ushort g_Wwh[CC * CI];       // W conv weight hi [o][d]
__device__ __align__(16) ushort g_Wwl[CC * CI];
__device__ __align__(16) ushort g_Qh[BB * NN * CI];   // theta hi  [b][n][d]  (hi only)
__device__ __align__(16) ushort g_Kh[BB * NN * CI];   // phi hi    [b][m][d]  (hi only)
__device__ __align__(16) ushort g_Gth[BB * CI * NN];  // g^T hi    [b][d][m]
__device__ __align__(16) ushort g_Yh[BB * NN * CI];   // attention out hi [b][n][d]
__device__ __align__(16) ushort g_Yl[BB * NN * CI];
__device__ __align__(16) float g_WY[BB * NN * CC];    // W conv out [b][n][o]
__device__ __align__(16) float g_psum[128 * CC];
__device__ __align__(16) float g_psq [128 * CC];
__device__ float g_mean[CC];
__device__ float g_rstd[CC];

// ---------------- helpers ----------------
__device__ __forceinline__ ushort bf16rn(float v) {
    uint u = __float_as_uint(v);
    return (ushort)((u + 0x7FFFu + ((u >> 16) & 1u)) >> 16);
}
__device__ __forceinline__ uint smem_u32(const void* p) {
    uint a;
    asm("{ .reg .u64 t; cvta.to.shared.u64 t, %1; cvt.u32.u64 %0, t; }" : "=r"(a) : "l"(p));
    return a;
}
__device__ __forceinline__ void cpa16(uint s, const void* g) {
    asm volatile("cp.async.cg.shared.global [%0], [%1], 16;" :: "r"(s), "l"(g) : "memory");
}
#define CP_COMMIT() asm volatile("cp.async.commit_group;" ::: "memory")
#define CP_WAIT0()  asm volatile("cp.async.wait_group 0;" ::: "memory")
#define CP_WAIT1()  asm volatile("cp.async.wait_group 1;" ::: "memory")

#define LDSM4(r0, r1, r2, r3, addr) \
    asm volatile("ldmatrix.sync.aligned.m8n8.x4.shared.b16 {%0,%1,%2,%3}, [%4];" \
        : "=r"(r0), "=r"(r1), "=r"(r2), "=r"(r3) : "r"(addr))

// pack2(lo, hi): bf16x2 with lo in low half
__device__ __forceinline__ uint pack2(float lo, float hi) {
    uint r;
    asm("cvt.rn.bf16x2.f32 %0, %1, %2;" : "=r"(r) : "f"(hi), "f"(lo));
    return r;
}
__device__ __forceinline__ void mma_bf(float& d0, float& d1, float& d2, float& d3,
                                       uint a0, uint a1, uint a2, uint a3,
                                       uint b0, uint b1) {
    asm volatile("mma.sync.aligned.m16n8k16.row.col.f32.bf16.bf16.f32 "
        "{%0,%1,%2,%3},{%4,%5,%6,%7},{%8,%9},{%0,%1,%2,%3};"
        : "+f"(d0), "+f"(d1), "+f"(d2), "+f"(d3)
        : "r"(a0), "r"(a1), "r"(a2), "r"(a3), "r"(b0), "r"(b1));
}

// ---------------- kernel 0a: transpose + split x -> bf16 hi/lo [b][n][c] ----------------
__global__ void __launch_bounds__(256) xcvt_kernel(const float* __restrict__ x)
{
    __shared__ float st[64 * 65];
    const int n0 = blockIdx.x * 64;
    const int c0 = blockIdx.y * 64;
    const int b  = blockIdx.z;
    const int tid = threadIdx.x;
#pragma unroll
    for (int r = 0; r < 16; r++) {
        int idx = tid + r * 256;
        int cc = idx >> 6, nl = idx & 63;
        st[nl * 65 + cc] = x[((size_t)(b * CC + c0 + cc)) * NN + n0 + nl];
    }
    __syncthreads();
#pragma unroll
    for (int r = 0; r < 16; r++) {
        int idx = tid + r * 256;
        int nl = idx >> 6, cc = idx & 63;
        float v = st[nl * 65 + cc];
        ushort h = bf16rn(v);
        ushort l = bf16rn(v - __uint_as_float(((uint)h) << 16));
        size_t o = ((size_t)(b * NN + n0 + nl)) * CC + c0 + cc;
        g_Xh[o] = h;
        g_Xl[o] = l;
    }
}

// ---------------- kernel 0b: split weights -> bf16 hi/lo ----------------
__global__ void __launch_bounds__(256) wcvt_kernel(
    const float* __restrict__ gw, const float* __restrict__ tw,
    const float* __restrict__ pw, const float* __restrict__ Ww)
{
    const int total = 3 * CI * CC + CC * CI;
    for (int idx = blockIdx.x * 256 + threadIdx.x; idx < total; idx += gridDim.x * 256) {
        float v;
        if (idx < 3 * CI * CC) {
            int which = idx / (CI * CC), r = idx % (CI * CC);
            v = (which == 0 ? gw : which == 1 ? tw : pw)[r];
            ushort h = bf16rn(v);
            g_PWh[idx] = h;
            g_PWl[idx] = bf16rn(v - __uint_as_float(((uint)h) << 16));
        } else {
            int r = idx - 3 * CI * CC;
            v = Ww[r];
            ushort h = bf16rn(v);
            g_Wwh[r] = h;
            g_Wwl[r] = bf16rn(v - __uint_as_float(((uint)h) << 16));
        }
    }
}

// ---------------- kernel 1: mma projections ----------------
#define PJ_XH(buf) ((buf) * 73728)
#define PJ_XL(buf) ((buf) * 73728 + 18432)
#define PJ_WH(buf) ((buf) * 73728 + 36864)
#define PJ_WL(buf) ((buf) * 73728 + 55296)
#define PROJ_SMEM (2 * 73728)

extern __shared__ char sm_p[];

__global__ void __launch_bounds__(256, 1) proj_kernel(
    const float* __restrict__ gb_, const float* __restrict__ tb_,
    const float* __restrict__ pb_)
{
    const int b  = blockIdx.y;
    const int n0 = blockIdx.x * 128;
    const int which = blockIdx.z;              // 0=g->Gt(hi), 1=theta->Q(hi), 2=phi->K(hi)
    const int tid = threadIdx.x;
    const int lane = tid & 31, warp = tid >> 5;
    const uint sb = smem_u32(sm_p);
    const float* bias = (which == 0) ? gb_ : (which == 1) ? tb_ : pb_;

    const char* Xh_g = (const char*)(g_Xh + (size_t)(b * NN + n0) * CC);
    const char* Xl_g = (const char*)(g_Xl + (size_t)(b * NN + n0) * CC);
    const char* Wh_g = (const char*)(g_PWh + which * CI * CC);
    const char* Wl_g = (const char*)(g_PWl + which * CI * CC);

    auto load_chunk = [&](int ch) {
        if (ch < 4) {
            int buf = ch & 1;
            int cb = ch * 128;
#pragma unroll
            for (int it = 0; it < 4; it++) {
                int u = tid + it * 256;
                int row = u >> 3, seg = u & 7;
                cpa16(sb + PJ_XH(buf) + row * 144 + seg * 16, Xh_g + (size_t)row * 512 + cb + seg * 16);
                cpa16(sb + PJ_XL(buf) + row * 144 + seg * 16, Xl_g + (size_t)row * 512 + cb + seg * 16);
                cpa16(sb + PJ_WH(buf) + row * 144 + seg * 16, Wh_g + (size_t)row * 512 + cb + seg * 16);
                cpa16(sb + PJ_WL(buf) + row * 144 + seg * 16, Wl_g + (size_t)row * 512 + cb + seg * 16);
            }
        }
        CP_COMMIT();
    };

    load_chunk(0);
    load_chunk(1);

    const int r0 = warp * 16 + (lane >> 2);
    float acc[16][4];
#pragma unroll
    for (int i = 0; i < 16; i++)
#pragma unroll
        for (int c = 0; c < 4; c++) acc[i][c] = 0.f;

    const uint qoff144 = (uint)(warp * 16 + (lane & 15)) * 144 + ((lane >> 4) << 4);
    const uint koff144 = (uint)((lane & 7) + ((lane >> 4) << 3)) * 144 + (((lane >> 3) & 1) << 4);

    for (int ch = 0; ch < 4; ch++) {
        CP_WAIT1();
        __syncthreads();
        int buf = ch & 1;
#pragma unroll
        for (int kt = 0; kt < 4; kt++) {
            uint ah0, ah1, ah2, ah3, al0, al1, al2, al3;
            LDSM4(ah0, ah1, ah2, ah3, sb + PJ_XH(buf) + qoff144 + kt * 32);
            LDSM4(al0, al1, al2, al3, sb + PJ_XL(buf) + qoff144 + kt * 32);
#pragma unroll
            for (int op = 0; op < 8; op++) {
                uint bh0, bh1, bh2, bh3, bl0, bl1, bl2, bl3;
                LDSM4(bh0, bh1, bh2, bh3, sb + PJ_WH(buf) + koff144 + (uint)op * 16 * 144 + kt * 32);
                LDSM4(bl0, bl1, bl2, bl3, sb + PJ_WL(buf) + koff144 + (uint)op * 16 * 144 + kt * 32);
                mma_bf(acc[2*op][0], acc[2*op][1], acc[2*op][2], acc[2*op][3],
                       ah0, ah1, ah2, ah3, bh0, bh1);
                mma_bf(acc[2*op][0], acc[2*op][1], acc[2*op][2], acc[2*op][3],
                       ah0, ah1, ah2, ah3, bl0, bl1);
                mma_bf(acc[2*op][0], acc[2*op][1], acc[2*op][2], acc[2*op][3],
                       al0, al1, al2, al3, bh0, bh1);
                mma_bf(acc[2*op+1][0], acc[2*op+1][1], acc[2*op+1][2], acc[2*op+1][3],
                       ah0, ah1, ah2, ah3, bh2, bh3);
                mma_bf(acc[2*op+1][0], acc[2*op+1][1], acc[2*op+1][2], acc[2*op+1][3],
                       ah0, ah1, ah2, ah3, bl2, bl3);
                mma_bf(acc[2*op+1][0], acc[2*op+1][1], acc[2*op+1][2], acc[2*op+1][3],
                       al0, al1, al2, al3, bh2, bh3);
            }
        }
        __syncthreads();
        load_chunk(ch + 2);
    }
    CP_WAIT0();

#pragma unroll
    for (int ot = 0; ot < 16; ot++) {
        int o = ot * 8 + (lane & 3) * 2;
        float b0 = bias[o], b1 = bias[o + 1];
        acc[ot][0] += b0; acc[ot][1] += b1;
        acc[ot][2] += b0; acc[ot][3] += b1;
    }

    if (which != 0) {
        // theta / phi: hi only, [n][d] layout
        uint* dh = (uint*)((which == 1) ? g_Qh : g_Kh) + (size_t)(b * NN + n0) * (CI / 2);
#pragma unroll
        for (int ot = 0; ot < 16; ot++) {
            uint i0 = (uint)r0 * 64 + ot * 4 + (lane & 3);
            uint i1 = i0 + 8 * 64;
            dh[i0] = pack2(acc[ot][0], acc[ot][1]);
            dh[i1] = pack2(acc[ot][2], acc[ot][3]);
        }
    } else {
        // g: hi-only transpose through smem
        ushort* st = (ushort*)sm_p;
        __syncthreads();
#pragma unroll
        for (int ot = 0; ot < 16; ot++) {
            int o = ot * 8 + (lane & 3) * 2;
#pragma unroll
            for (int c = 0; c < 4; c++) {
                int oo = o + (c & 1);
                int rr = (c < 2) ? r0 : (r0 + 8);
                st[oo * 136 + rr] = bf16rn(acc[ot][c]);
            }
        }
        __syncthreads();
#pragma unroll
        for (int it = 0; it < 8; it++) {
            int u = tid + it * 256;
            int o = u >> 4, seg = u & 15;
            *(uint4*)((char*)g_Gth + (((size_t)(b * CI + o)) * NN + n0) * 2 + seg * 16)
                = *(const uint4*)((const char*)st + o * 272 + seg * 16);
        }
    }
}

// ---------------- kernel 2: flash attention (ldmatrix, 3-stage, hi-only S) ----------------
#define SQH 0
#define SKH(s) (34816 + (s) * 17408)
#define SGH(s) (87040 + (s) * 18432)
#define ATTN_SMEM 142336
#define KTILES 64

extern __shared__ char sm_a[];

__global__ void __launch_bounds__(256, 1) attn_kernel()
{
    const int b  = blockIdx.y;
    const int qt = blockIdx.x;
    const int tid = threadIdx.x;
    const int lane = tid & 31, warp = tid >> 5;
    const uint sb = smem_u32(sm_a);

    const size_t qbase = (size_t)(b * NN + qt * 128) * CI;
    const char* Qh_g = (const char*)(g_Qh + qbase);
    const char* gh_g = (const char*)(g_Gth + (size_t)(b * CI) * NN);

    auto load_stage = [&](int kt, int s) {
        const char* khs = (const char*)(g_Kh + (size_t)(b * NN + kt * 64) * CI);
#pragma unroll
        for (int it = 0; it < 2; it++) {
            int u = tid + it * 256;
            int row = u >> 2, ch = u & 3;          // 64 rows x 4 segs of 64B? no: 16B segs
            // 64 rows * 16 segs = 1024 sixteen-byte segs; 256 thr x 4 iters
        }
#pragma unroll
        for (int it = 0; it < 4; it++) {
            int u = tid + it * 256;
            int row = u >> 4, ch = u & 15;
            cpa16(sb + SKH(s) + row * 272 + ch * 16, khs + row * 256 + ch * 16);
        }
#pragma unroll
        for (int it = 0; it < 4; it++) {
            int u = tid + it * 256;
            int row = u >> 3, ch = u & 7;
            cpa16(sb + SGH(s) + row * 144 + ch * 16, gh_g + (size_t)row * NN * 2 + kt * 128 + ch * 16);
        }
    };

    // prologue: Q + stage0 in group0, stage1 in group1
#pragma unroll
    for (int it = 0; it < 8; it++) {
        int u = tid + it * 256;
        int row = u >> 4, ch = u & 15;
        cpa16(sb + SQH + row * 272 + ch * 16, Qh_g + row * 256 + ch * 16);
    }
    load_stage(0, 0);
    CP_COMMIT();
    load_stage(1, 1);
    CP_COMMIT();

    const int r0 = warp * 16 + (lane >> 2);
    float o[16][4];
#pragma unroll
    for (int d = 0; d < 16; d++)
#pragma unroll
        for (int c = 0; c < 4; c++) o[d][c] = 0.f;
    float l0 = 0.f, l1 = 0.f;

    const uint qoff = (uint)(warp * 16 + (lane & 15)) * 272 + ((lane >> 4) << 4);
    const uint koff = (uint)((lane & 7) + ((lane >> 4) << 3)) * 272 + (((lane >> 3) & 1) << 4);
    const uint goff = (uint)((lane & 7) + ((lane >> 4) << 3)) * 144 + (((lane >> 3) & 1) << 4);

    int stage = 0;
    for (int t = 0; t < KTILES; t++) {
        CP_WAIT1();
        __syncthreads();
        int pst = stage + 2 >= 3 ? stage - 1 : stage + 2;
        if (t + 2 < KTILES) load_stage(t + 2, pst);
        CP_COMMIT();

        const uint skh = sb + SKH(stage);
        const uint sgh = sb + SGH(stage);

        float acc[8][4];
#pragma unroll
        for (int nt = 0; nt < 8; nt++)
#pragma unroll
            for (int c = 0; c < 4; c++) acc[nt][c] = 0.f;

        // S = Q_hi * K_hi  (consistent-weights mechanism absorbs both lo terms)
#pragma unroll
        for (int kt = 0; kt < 8; kt++) {
            uint ah0, ah1, ah2, ah3;
            LDSM4(ah0, ah1, ah2, ah3, sb + SQH + qoff + kt * 32);
#pragma unroll
            for (int np = 0; np < 4; np++) {
                uint bh0, bh1, bh2, bh3;
                LDSM4(bh0, bh1, bh2, bh3, skh + koff + (uint)np * 16 * 272 + kt * 32);
                mma_bf(acc[2*np][0], acc[2*np][1], acc[2*np][2], acc[2*np][3],
                       ah0, ah1, ah2, ah3, bh0, bh1);
                mma_bf(acc[2*np+1][0], acc[2*np+1][1], acc[2*np+1][2], acc[2*np+1][3],
                       ah0, ah1, ah2, ah3, bh2, bh3);
            }
        }

        // softmax: exp, round to bf16; l sums the ROUNDED values (consistency)
        uint ph[8][2];
#pragma unroll
        for (int nt = 0; nt < 8; nt++) {
            float p0 = __expf(acc[nt][0]);
            float p1 = __expf(acc[nt][1]);
            float p2 = __expf(acc[nt][2]);
            float p3 = __expf(acc[nt][3]);
            uint h01 = pack2(p0, p1);
            uint h23 = pack2(p2, p3);
            l0 += __uint_as_float(h01 << 16) + __uint_as_float(h01 & 0xffff0000u);
            l1 += __uint_as_float(h23 << 16) + __uint_as_float(h23 & 0xffff0000u);
            ph[nt][0] = h01; ph[nt][1] = h23;
        }

        // O += P_hi * G_hi
#pragma unroll
        for (int kt2 = 0; kt2 < 4; kt2++) {
            uint ah0 = ph[2 * kt2][0], ah1 = ph[2 * kt2][1];
            uint ah2 = ph[2 * kt2 + 1][0], ah3 = ph[2 * kt2 + 1][1];
#pragma unroll
            for (int dp = 0; dp < 8; dp++) {
                uint g0, g1, g2, g3;
                LDSM4(g0, g1, g2, g3, sgh + goff + (uint)dp * 16 * 144 + kt2 * 32);
                mma_bf(o[2*dp][0], o[2*dp][1], o[2*dp][2], o[2*dp][3],
                       ah0, ah1, ah2, ah3, g0, g1);
                mma_bf(o[2*dp+1][0], o[2*dp+1][1], o[2*dp+1][2], o[2*dp+1][3],
                       ah0, ah1, ah2, ah3, g2, g3);
            }
        }

        stage = (stage + 1 == 3) ? 0 : stage + 1;
    }

    // epilogue: quad-reduce l, normalize, emit Y bf16 hi/lo
    l0 += __shfl_xor_sync(0xffffffffu, l0, 1);
    l0 += __shfl_xor_sync(0xffffffffu, l0, 2);
    l1 += __shfl_xor_sync(0xffffffffu, l1, 1);
    l1 += __shfl_xor_sync(0xffffffffu, l1, 2);
    const float inv0 = 1.0f / l0, inv1 = 1.0f / l1;

    const uint row0 = (uint)(qt * 128 + r0);
    uint* yh = (uint*)g_Yh + (size_t)b * NN * (CI / 2);
    uint* yl = (uint*)g_Yl + (size_t)b * NN * (CI / 2);
#pragma unroll
    for (int dn = 0; dn < 16; dn++) {
        uint i0 = row0 * 64 + dn * 4 + (lane & 3);
        uint i1 = i0 + 8 * 64;
        float v0 = o[dn][0] * inv0, v1 = o[dn][1] * inv0;
        float v2 = o[dn][2] * inv1, v3 = o[dn][3] * inv1;
        uint h0 = pack2(v0, v1), h1 = pack2(v2, v3);
        float e0 = v0 - __uint_as_float(h0 << 16);
        float e1 = v1 - __uint_as_float(h0 & 0xffff0000u);
        float e2 = v2 - __uint_as_float(h1 << 16);
        float e3 = v3 - __uint_as_float(h1 & 0xffff0000u);
        yh[i0] = h0; yl[i0] = pack2(e0, e1);
        yh[i1] = h1; yl[i1] = pack2(e2, e3);
    }
}

// ---------------- kernel 3: mma wgemm (ldmatrix) ----------------
#define WG_YH 0
#define WG_YL 34816
#define WG_WH 69632
#define WG_WL 104448
#define WG_SMEM 139264

extern __shared__ char sm_w[];

__global__ void __launch_bounds__(256, 1) wgemm_kernel(const float* __restrict__ Wb)
{
    const int b  = blockIdx.z;
    const int oh = blockIdx.y;
    const int n0 = blockIdx.x * 128;
    const int tid = threadIdx.x;
    const int lane = tid & 31, warp = tid >> 5;
    const uint sb = smem_u32(sm_w);

    {
        const char* yh = (const char*)(g_Yh + (size_t)(b * NN + n0) * CI);
        const char* yl = (const char*)(g_Yl + (size_t)(b * NN + n0) * CI);
        const char* wh = (const char*)(g_Wwh + (size_t)(oh * 128) * CI);
        const char* wl = (const char*)(g_Wwl + (size_t)(oh * 128) * CI);
#pragma unroll
        for (int it = 0; it < 8; it++) {
            int u = tid + it * 256;
            int row = u >> 4, ch = u & 15;
            cpa16(sb + WG_YH + row * 272 + ch * 16, yh + (size_t)row * 256 + ch * 16);
            cpa16(sb + WG_YL + row * 272 + ch * 16, yl + (size_t)row * 256 + ch * 16);
            cpa16(sb + WG_WH + row * 272 + ch * 16, wh + (size_t)row * 256 + ch * 16);
            cpa16(sb + WG_WL + row * 272 + ch * 16, wl + (size_t)row * 256 + ch * 16);
        }
    }
    CP_COMMIT();
    CP_WAIT0();
    __syncthreads();

    const int r0 = warp * 16 + (lane >> 2);
    float acc[16][4];
#pragma unroll
    for (int i = 0; i < 16; i++)
#pragma unroll
        for (int c = 0; c < 4; c++) acc[i][c] = 0.f;

    const uint qoff = (uint)(warp * 16 + (lane & 15)) * 272 + ((lane >> 4) << 4);
    const uint koff = (uint)((lane & 7) + ((lane >> 4) << 3)) * 272 + (((lane >> 3) & 1) << 4);

#pragma unroll
    for (int kt = 0; kt < 8; kt++) {
        uint ah0, ah1, ah2, ah3, al0, al1, al2, al3;
        LDSM4(ah0, ah1, ah2, ah3, sb + WG_YH + qoff + kt * 32);
        LDSM4(al0, al1, al2, al3, sb + WG_YL + qoff + kt * 32);
#pragma unroll
        for (int op = 0; op < 8; op++) {
            uint bh0, bh1, bh2, bh3, bl0, bl1, bl2, bl3;
            LDSM4(bh0, bh1, bh2, bh3, sb + WG_WH + koff + (uint)op * 16 * 272 + kt * 32);
            LDSM4(bl0, bl1, bl2, bl3, sb + WG_WL + koff + (uint)op * 16 * 272 + kt * 32);
            mma_bf(acc[2*op][0], acc[2*op][1], acc[2*op][2], acc[2*op][3],
                   ah0, ah1, ah2, ah3, bh0, bh1);
            mma_bf(acc[2*op][0], acc[2*op][1], acc[2*op][2], acc[2*op][3],
                   ah0, ah1, ah2, ah3, bl0, bl1);
            mma_bf(acc[2*op][0], acc[2*op][1], acc[2*op][2], acc[2*op][3],
                   al0, al1, al2, al3, bh0, bh1);
            mma_bf(acc[2*op+1][0], acc[2*op+1][1], acc[2*op+1][2], acc[2*op+1][3],
                   ah0, ah1, ah2, ah3, bh2, bh3);
            mma_bf(acc[2*op+1][0], acc[2*op+1][1], acc[2*op+1][2], acc[2*op+1][3],
                   ah0, ah1, ah2, ah3, bl2, bl3);
            mma_bf(acc[2*op+1][0], acc[2*op+1][1], acc[2*op+1][2], acc[2*op+1][3],
                   al0, al1, al2, al3, bh2, bh3);
        }
    }

    float* wy = g_WY + (size_t)(b * NN + n0) * CC + oh * 128;
#pragma unroll
    for (int ot = 0; ot < 16; ot++) {
        int o = ot * 8 + (lane & 3) * 2;
        float b0 = Wb[oh * 128 + o], b1 = Wb[oh * 128 + o + 1];
        *(float2*)(wy + (size_t)r0 * CC + o) = make_float2(acc[ot][0] + b0, acc[ot][1] + b1);
        *(float2*)(wy + (size_t)(r0 + 8) * CC + o) = make_float2(acc[ot][2] + b0, acc[ot][3] + b1);
    }
}

// ---------------- kernel 4a/4b: deterministic BN stats ----------------
__global__ void __launch_bounds__(256) stats1_kernel()
{
    const int blk = blockIdx.x;
    const int t = threadIdx.x;
    float s = 0.f, q = 0.f;
    const float* base = g_WY + (size_t)blk * 128 * CC + t;
    for (int r = 0; r < 128; r++) {
        float v = base[(size_t)r * CC];
        s += v; q += v * v;
    }
    g_psum[blk * CC + t] = s;
    g_psq [blk * CC + t] = q;
}
__global__ void __launch_bounds__(256) stats2_kernel()
{
    const int t = threadIdx.x;
    float s = 0.f, q = 0.f;
    for (int p = 0; p < 128; p++) {
        s += g_psum[p * CC + t];
        q += g_psq [p * CC + t];
    }
    const float invn = 1.0f / (float)(BB * NN);
    float mean = s * invn;
    float var  = q * invn - mean * mean;
    g_mean[t] = mean;
    g_rstd[t] = rsqrtf(var + BN_EPS);
}

// ---------------- kernel 5: BN apply + scale + residual (with transpose) ----------------
__global__ void __launch_bounds__(256) apply_kernel(
    const float* __restrict__ x,
    const float* __restrict__ gamma, const float* __restrict__ beta,
    const float* __restrict__ scale, float* __restrict__ out)
{
    __shared__ float st[64 * 65];
    const int n0 = blockIdx.x * 64;
    const int c0 = blockIdx.y * 64;
    const int b  = blockIdx.z;
    const int tid = threadIdx.x;
    const float s = scale[0];

#pragma unroll
    for (int r = 0; r < 16; r++) {
        int idx = tid + r * 256;
        int nl = idx >> 6, cc = idx & 63;
        st[cc * 65 + nl] = g_WY[((size_t)(b * NN + n0 + nl)) * CC + c0 + cc];
    }
    __syncthreads();
#pragma unroll
    for (int r = 0; r < 16; r++) {
        int idx = tid + r * 256;
        int cc = idx >> 6, nl = idx & 63;
        int c = c0 + cc;
        float wv = st[cc * 65 + nl];
        float v = s * ((wv - g_mean[c]) * g_rstd[c] * gamma[c] + beta[c])
                + x[((size_t)(b * CC + c)) * NN + n0 + nl];
        out[((size_t)(b * CC + c)) * NN + n0 + nl] = v;
    }
}

// ---------------- launcher ----------------
extern "C" void kernel_launch(void* const* d_in, const int* in_sizes, int n_in,
                              void* d_out, int out_size)
{
    const float* x     = (const float*)d_in[0];
    const float* gw    = (const float*)d_in[1];
    const float* gb    = (const float*)d_in[2];
    const float* tw    = (const float*)d_in[3];
    const float* tb    = (const float*)d_in[4];
    const float* pw    = (const float*)d_in[5];
    const float* pb    = (const float*)d_in[6];
    const float* Ww    = (const float*)d_in[7];
    const float* Wb    = (const float*)d_in[8];
    const float* gamma = (const float*)d_in[9];
    const float* beta  = (const float*)d_in[10];
    const float* scale = (const float*)d_in[11];
    float* out = (float*)d_out;

    cudaFuncSetAttribute(proj_kernel,
                         cudaFuncAttributeMaxDynamicSharedMemorySize, PROJ_SMEM);
    cudaFuncSetAttribute(attn_kernel,
                         cudaFuncAttributeMaxDynamicSharedMemorySize, ATTN_SMEM);
    cudaFuncSetAttribute(wgemm_kernel,
                         cudaFuncAttributeMaxDynamicSharedMemorySize, WG_SMEM);

    xcvt_kernel<<<dim3(NN / 64, CC / 64, BB), 256>>>(x);
    wcvt_kernel<<<64, 256>>>(gw, tw, pw, Ww);
    proj_kernel<<<dim3(NN / 128, BB, 3), 256, PROJ_SMEM>>>(gb, tb, pb);
    attn_kernel<<<dim3(NN / 128, BB), 256, ATTN_SMEM>>>();
    wgemm_kernel<<<dim3(NN / 128, 2, BB), 256, WG_SMEM>>>(Wb);
    stats1_kernel<<<128, 256>>>();
    stats2_kernel<<<1, 256>>>();
    apply_kernel<<<dim3(NN / 64, CC / 64, BB), 256>>>(x, gamma, beta, scale, out);
}

// round 15
// speedup vs baseline: 1.4571x; 1.0400x over previous
#include <cuda_runtime.h>

#define BB 4
#define CC 256
#define CI 128
#define NN 4096
#define BN_EPS 1e-5f

typedef unsigned int uint;
typedef unsigned short ushort;

// ---------------- scratch (no allocations allowed) ----------------
__device__ __align__(16) ushort g_Xh[BB * NN * CC];   // x^T hi [b][n][c]
__device__ __align__(16) ushort g_Xl[BB * NN * CC];
__device__ __align__(16) ushort g_PWh[3 * CI * CC];   // proj weights hi (g, theta, phi) [which][o][c]
__device__ __align__(16) ushort g_PWl[3 * CI * CC];
__device__ __align__(16) ushort g_Wwh[CC * CI];       // W conv weight hi [o][d]
__device__ __align__(16) ushort g_Wwl[CC * CI];
__device__ __align__(16) ushort g_Qh[BB * NN * CI];   // theta hi  [b][n][d]  (hi only)
__device__ __align__(16) ushort g_Kh[BB * NN * CI];   // phi hi    [b][m][d]  (hi only)
__device__ __align__(16) ushort g_Gth[BB * CI * NN];  // g^T hi    [b][d][m]
__device__ __align__(16) ushort g_Yh[BB * NN * CI];   // attention out hi [b][n][d]
__device__ __align__(16) ushort g_Yl[BB * NN * CI];
__device__ __align__(16) float g_WY[BB * NN * CC];    // W conv out [b][n][o]
__device__ __align__(16) float g_psum[128 * CC];
__device__ __align__(16) float g_psq [128 * CC];
__device__ float g_mean[CC];
__device__ float g_rstd[CC];

// ---------------- helpers ----------------
__device__ __forceinline__ ushort bf16rn(float v) {
    uint u = __float_as_uint(v);
    return (ushort)((u + 0x7FFFu + ((u >> 16) & 1u)) >> 16);
}
__device__ __forceinline__ uint smem_u32(const void* p) {
    uint a;
    asm("{ .reg .u64 t; cvta.to.shared.u64 t, %1; cvt.u32.u64 %0, t; }" : "=r"(a) : "l"(p));
    return a;
}
__device__ __forceinline__ void cpa16(uint s, const void* g) {
    asm volatile("cp.async.cg.shared.global [%0], [%1], 16;" :: "r"(s), "l"(g) : "memory");
}
#define CP_COMMIT() asm volatile("cp.async.commit_group;" ::: "memory")
#define CP_WAIT0()  asm volatile("cp.async.wait_group 0;" ::: "memory")
#define CP_WAIT1()  asm volatile("cp.async.wait_group 1;" ::: "memory")

#define LDSM4(r0, r1, r2, r3, addr) \
    asm volatile("ldmatrix.sync.aligned.m8n8.x4.shared.b16 {%0,%1,%2,%3}, [%4];" \
        : "=r"(r0), "=r"(r1), "=r"(r2), "=r"(r3) : "r"(addr))

// pack2(lo, hi): bf16x2 with lo in low half
__device__ __forceinline__ uint pack2(float lo, float hi) {
    uint r;
    asm("cvt.rn.bf16x2.f32 %0, %1, %2;" : "=r"(r) : "f"(hi), "f"(lo));
    return r;
}
__device__ __forceinline__ void mma_bf(float& d0, float& d1, float& d2, float& d3,
                                       uint a0, uint a1, uint a2, uint a3,
                                       uint b0, uint b1) {
    asm volatile("mma.sync.aligned.m16n8k16.row.col.f32.bf16.bf16.f32 "
        "{%0,%1,%2,%3},{%4,%5,%6,%7},{%8,%9},{%0,%1,%2,%3};"
        : "+f"(d0), "+f"(d1), "+f"(d2), "+f"(d3)
        : "r"(a0), "r"(a1), "r"(a2), "r"(a3), "r"(b0), "r"(b1));
}

// ---------------- kernel 0a: transpose + split x -> bf16 hi/lo [b][n][c] ----------------
__global__ void __launch_bounds__(256) xcvt_kernel(const float* __restrict__ x)
{
    __shared__ float st[64 * 65];
    const int n0 = blockIdx.x * 64;
    const int c0 = blockIdx.y * 64;
    const int b  = blockIdx.z;
    const int tid = threadIdx.x;
#pragma unroll
    for (int r = 0; r < 16; r++) {
        int idx = tid + r * 256;
        int cc = idx >> 6, nl = idx & 63;
        st[nl * 65 + cc] = x[((size_t)(b * CC + c0 + cc)) * NN + n0 + nl];
    }
    __syncthreads();
#pragma unroll
    for (int r = 0; r < 16; r++) {
        int idx = tid + r * 256;
        int nl = idx >> 6, cc = idx & 63;
        float v = st[nl * 65 + cc];
        ushort h = bf16rn(v);
        ushort l = bf16rn(v - __uint_as_float(((uint)h) << 16));
        size_t o = ((size_t)(b * NN + n0 + nl)) * CC + c0 + cc;
        g_Xh[o] = h;
        g_Xl[o] = l;
    }
}

// ---------------- kernel 0b: split weights -> bf16 hi/lo ----------------
__global__ void __launch_bounds__(256) wcvt_kernel(
    const float* __restrict__ gw, const float* __restrict__ tw,
    const float* __restrict__ pw, const float* __restrict__ Ww)
{
    const int total = 3 * CI * CC + CC * CI;
    for (int idx = blockIdx.x * 256 + threadIdx.x; idx < total; idx += gridDim.x * 256) {
        float v;
        if (idx < 3 * CI * CC) {
            int which = idx / (CI * CC), r = idx % (CI * CC);
            v = (which == 0 ? gw : which == 1 ? tw : pw)[r];
            ushort h = bf16rn(v);
            g_PWh[idx] = h;
            g_PWl[idx] = bf16rn(v - __uint_as_float(((uint)h) << 16));
        } else {
            int r = idx - 3 * CI * CC;
            v = Ww[r];
            ushort h = bf16rn(v);
            g_Wwh[r] = h;
            g_Wwl[r] = bf16rn(v - __uint_as_float(((uint)h) << 16));
        }
    }
}

// ---------------- kernel 1: mma projections ----------------
#define PJ_XH(buf) ((buf) * 73728)
#define PJ_XL(buf) ((buf) * 73728 + 18432)
#define PJ_WH(buf) ((buf) * 73728 + 36864)
#define PJ_WL(buf) ((buf) * 73728 + 55296)
#define PROJ_SMEM (2 * 73728)

extern __shared__ char sm_p[];

__global__ void __launch_bounds__(256, 1) proj_kernel(
    const float* __restrict__ gb_, const float* __restrict__ tb_,
    const float* __restrict__ pb_)
{
    const int b  = blockIdx.y;
    const int n0 = blockIdx.x * 128;
    const int which = blockIdx.z;              // 0=g->Gt(hi), 1=theta->Q(hi), 2=phi->K(hi)
    const int tid = threadIdx.x;
    const int lane = tid & 31, warp = tid >> 5;
    const uint sb = smem_u32(sm_p);
    const float* bias = (which == 0) ? gb_ : (which == 1) ? tb_ : pb_;

    const char* Xh_g = (const char*)(g_Xh + (size_t)(b * NN + n0) * CC);
    const char* Xl_g = (const char*)(g_Xl + (size_t)(b * NN + n0) * CC);
    const char* Wh_g = (const char*)(g_PWh + which * CI * CC);
    const char* Wl_g = (const char*)(g_PWl + which * CI * CC);

    auto load_chunk = [&](int ch) {
        if (ch < 4) {
            int buf = ch & 1;
            int cb = ch * 128;
#pragma unroll
            for (int it = 0; it < 4; it++) {
                int u = tid + it * 256;
                int row = u >> 3, seg = u & 7;
                cpa16(sb + PJ_XH(buf) + row * 144 + seg * 16, Xh_g + (size_t)row * 512 + cb + seg * 16);
                cpa16(sb + PJ_XL(buf) + row * 144 + seg * 16, Xl_g + (size_t)row * 512 + cb + seg * 16);
                cpa16(sb + PJ_WH(buf) + row * 144 + seg * 16, Wh_g + (size_t)row * 512 + cb + seg * 16);
                cpa16(sb + PJ_WL(buf) + row * 144 + seg * 16, Wl_g + (size_t)row * 512 + cb + seg * 16);
            }
        }
        CP_COMMIT();
    };

    load_chunk(0);
    load_chunk(1);

    const int r0 = warp * 16 + (lane >> 2);
    float acc[16][4];
#pragma unroll
    for (int i = 0; i < 16; i++)
#pragma unroll
        for (int c = 0; c < 4; c++) acc[i][c] = 0.f;

    const uint qoff144 = (uint)(warp * 16 + (lane & 15)) * 144 + ((lane >> 4) << 4);
    const uint koff144 = (uint)((lane & 7) + ((lane >> 4) << 3)) * 144 + (((lane >> 3) & 1) << 4);

    for (int ch = 0; ch < 4; ch++) {
        CP_WAIT1();
        __syncthreads();
        int buf = ch & 1;
#pragma unroll
        for (int kt = 0; kt < 4; kt++) {
            uint ah0, ah1, ah2, ah3, al0, al1, al2, al3;
            LDSM4(ah0, ah1, ah2, ah3, sb + PJ_XH(buf) + qoff144 + kt * 32);
            LDSM4(al0, al1, al2, al3, sb + PJ_XL(buf) + qoff144 + kt * 32);
#pragma unroll
            for (int op = 0; op < 8; op++) {
                uint bh0, bh1, bh2, bh3, bl0, bl1, bl2, bl3;
                LDSM4(bh0, bh1, bh2, bh3, sb + PJ_WH(buf) + koff144 + (uint)op * 16 * 144 + kt * 32);
                LDSM4(bl0, bl1, bl2, bl3, sb + PJ_WL(buf) + koff144 + (uint)op * 16 * 144 + kt * 32);
                mma_bf(acc[2*op][0], acc[2*op][1], acc[2*op][2], acc[2*op][3],
                       ah0, ah1, ah2, ah3, bh0, bh1);
                mma_bf(acc[2*op][0], acc[2*op][1], acc[2*op][2], acc[2*op][3],
                       ah0, ah1, ah2, ah3, bl0, bl1);
                mma_bf(acc[2*op][0], acc[2*op][1], acc[2*op][2], acc[2*op][3],
                       al0, al1, al2, al3, bh0, bh1);
                mma_bf(acc[2*op+1][0], acc[2*op+1][1], acc[2*op+1][2], acc[2*op+1][3],
                       ah0, ah1, ah2, ah3, bh2, bh3);
                mma_bf(acc[2*op+1][0], acc[2*op+1][1], acc[2*op+1][2], acc[2*op+1][3],
                       ah0, ah1, ah2, ah3, bl2, bl3);
                mma_bf(acc[2*op+1][0], acc[2*op+1][1], acc[2*op+1][2], acc[2*op+1][3],
                       al0, al1, al2, al3, bh2, bh3);
            }
        }
        __syncthreads();
        load_chunk(ch + 2);
    }
    CP_WAIT0();

#pragma unroll
    for (int ot = 0; ot < 16; ot++) {
        int o = ot * 8 + (lane & 3) * 2;
        float b0 = bias[o], b1 = bias[o + 1];
        acc[ot][0] += b0; acc[ot][1] += b1;
        acc[ot][2] += b0; acc[ot][3] += b1;
    }

    if (which != 0) {
        // theta / phi: hi only, [n][d] layout
        uint* dh = (uint*)((which == 1) ? g_Qh : g_Kh) + (size_t)(b * NN + n0) * (CI / 2);
#pragma unroll
        for (int ot = 0; ot < 16; ot++) {
            uint i0 = (uint)r0 * 64 + ot * 4 + (lane & 3);
            uint i1 = i0 + 8 * 64;
            dh[i0] = pack2(acc[ot][0], acc[ot][1]);
            dh[i1] = pack2(acc[ot][2], acc[ot][3]);
        }
    } else {
        // g: hi-only transpose through smem
        ushort* st = (ushort*)sm_p;
        __syncthreads();
#pragma unroll
        for (int ot = 0; ot < 16; ot++) {
            int o = ot * 8 + (lane & 3) * 2;
#pragma unroll
            for (int c = 0; c < 4; c++) {
                int oo = o + (c & 1);
                int rr = (c < 2) ? r0 : (r0 + 8);
                st[oo * 136 + rr] = bf16rn(acc[ot][c]);
            }
        }
        __syncthreads();
#pragma unroll
        for (int it = 0; it < 8; it++) {
            int u = tid + it * 256;
            int o = u >> 4, seg = u & 15;
            *(uint4*)((char*)g_Gth + (((size_t)(b * CI + o)) * NN + n0) * 2 + seg * 16)
                = *(const uint4*)((const char*)st + o * 272 + seg * 16);
        }
    }
}

// ---------------- kernel 2: flash attention (ldmatrix, 3-stage, Q in registers) ----------------
#define SQH 0
#define SKH(s) (34816 + (s) * 17408)
#define SGH(s) (87040 + (s) * 18432)
#define ATTN_SMEM 142336
#define KTILES 64

extern __shared__ char sm_a[];

__global__ void __launch_bounds__(256, 1) attn_kernel()
{
    const int b  = blockIdx.y;
    const int qt = blockIdx.x;
    const int tid = threadIdx.x;
    const int lane = tid & 31, warp = tid >> 5;
    const uint sb = smem_u32(sm_a);

    const size_t qbase = (size_t)(b * NN + qt * 128) * CI;
    const char* Qh_g = (const char*)(g_Qh + qbase);
    const char* gh_g = (const char*)(g_Gth + (size_t)(b * CI) * NN);

    auto load_stage = [&](int kt, int s) {
        const char* khs = (const char*)(g_Kh + (size_t)(b * NN + kt * 64) * CI);
#pragma unroll
        for (int it = 0; it < 4; it++) {
            int u = tid + it * 256;
            int row = u >> 4, ch = u & 15;
            cpa16(sb + SKH(s) + row * 272 + ch * 16, khs + row * 256 + ch * 16);
        }
#pragma unroll
        for (int it = 0; it < 4; it++) {
            int u = tid + it * 256;
            int row = u >> 3, ch = u & 7;
            cpa16(sb + SGH(s) + row * 144 + ch * 16, gh_g + (size_t)row * NN * 2 + kt * 128 + ch * 16);
        }
    };

    // prologue: Q + stage0 in group0, stage1 in group1
#pragma unroll
    for (int it = 0; it < 8; it++) {
        int u = tid + it * 256;
        int row = u >> 4, ch = u & 15;
        cpa16(sb + SQH + row * 272 + ch * 16, Qh_g + row * 256 + ch * 16);
    }
    load_stage(0, 0);
    CP_COMMIT();
    load_stage(1, 1);
    CP_COMMIT();

    const int r0 = warp * 16 + (lane >> 2);
    float o[16][4];
#pragma unroll
    for (int d = 0; d < 16; d++)
#pragma unroll
        for (int c = 0; c < 4; c++) o[d][c] = 0.f;
    float l0 = 0.f, l1 = 0.f;

    const uint qoff = (uint)(warp * 16 + (lane & 15)) * 272 + ((lane >> 4) << 4);
    const uint koff = (uint)((lane & 7) + ((lane >> 4) << 3)) * 272 + (((lane >> 3) & 1) << 4);
    const uint goff = (uint)((lane & 7) + ((lane >> 4) << 3)) * 144 + (((lane >> 3) & 1) << 4);

    // hoist Q fragments into registers (iteration-invariant)
    CP_WAIT1();            // group0 (Q + stage0) complete
    __syncthreads();
    uint qf[8][4];
#pragma unroll
    for (int kt = 0; kt < 8; kt++)
        LDSM4(qf[kt][0], qf[kt][1], qf[kt][2], qf[kt][3], sb + SQH + qoff + kt * 32);

    int stage = 0;
    for (int t = 0; t < KTILES; t++) {
        CP_WAIT1();
        __syncthreads();
        int pst = stage + 2 >= 3 ? stage - 1 : stage + 2;
        if (t + 2 < KTILES) load_stage(t + 2, pst);
        CP_COMMIT();

        const uint skh = sb + SKH(stage);
        const uint sgh = sb + SGH(stage);

        float acc[8][4];
#pragma unroll
        for (int nt = 0; nt < 8; nt++)
#pragma unroll
            for (int c = 0; c < 4; c++) acc[nt][c] = 0.f;

        // S = Q_hi * K_hi
#pragma unroll
        for (int kt = 0; kt < 8; kt++) {
#pragma unroll
            for (int np = 0; np < 4; np++) {
                uint bh0, bh1, bh2, bh3;
                LDSM4(bh0, bh1, bh2, bh3, skh + koff + (uint)np * 16 * 272 + kt * 32);
                mma_bf(acc[2*np][0], acc[2*np][1], acc[2*np][2], acc[2*np][3],
                       qf[kt][0], qf[kt][1], qf[kt][2], qf[kt][3], bh0, bh1);
                mma_bf(acc[2*np+1][0], acc[2*np+1][1], acc[2*np+1][2], acc[2*np+1][3],
                       qf[kt][0], qf[kt][1], qf[kt][2], qf[kt][3], bh2, bh3);
            }
        }

        // softmax: exp, round to bf16; l sums the ROUNDED values (consistency)
        uint ph[8][2];
#pragma unroll
        for (int nt = 0; nt < 8; nt++) {
            float p0 = __expf(acc[nt][0]);
            float p1 = __expf(acc[nt][1]);
            float p2 = __expf(acc[nt][2]);
            float p3 = __expf(acc[nt][3]);
            uint h01 = pack2(p0, p1);
            uint h23 = pack2(p2, p3);
            l0 += __uint_as_float(h01 << 16) + __uint_as_float(h01 & 0xffff0000u);
            l1 += __uint_as_float(h23 << 16) + __uint_as_float(h23 & 0xffff0000u);
            ph[nt][0] = h01; ph[nt][1] = h23;
        }

        // O += P_hi * G_hi
#pragma unroll
        for (int kt2 = 0; kt2 < 4; kt2++) {
            uint ah0 = ph[2 * kt2][0], ah1 = ph[2 * kt2][1];
            uint ah2 = ph[2 * kt2 + 1][0], ah3 = ph[2 * kt2 + 1][1];
#pragma unroll
            for (int dp = 0; dp < 8; dp++) {
                uint g0, g1, g2, g3;
                LDSM4(g0, g1, g2, g3, sgh + goff + (uint)dp * 16 * 144 + kt2 * 32);
                mma_bf(o[2*dp][0], o[2*dp][1], o[2*dp][2], o[2*dp][3],
                       ah0, ah1, ah2, ah3, g0, g1);
                mma_bf(o[2*dp+1][0], o[2*dp+1][1], o[2*dp+1][2], o[2*dp+1][3],
                       ah0, ah1, ah2, ah3, g2, g3);
            }
        }

        stage = (stage + 1 == 3) ? 0 : stage + 1;
    }

    // epilogue: quad-reduce l, normalize, emit Y bf16 hi/lo
    l0 += __shfl_xor_sync(0xffffffffu, l0, 1);
    l0 += __shfl_xor_sync(0xffffffffu, l0, 2);
    l1 += __shfl_xor_sync(0xffffffffu, l1, 1);
    l1 += __shfl_xor_sync(0xffffffffu, l1, 2);
    const float inv0 = 1.0f / l0, inv1 = 1.0f / l1;

    const uint row0 = (uint)(qt * 128 + r0);
    uint* yh = (uint*)g_Yh + (size_t)b * NN * (CI / 2);
    uint* yl = (uint*)g_Yl + (size_t)b * NN * (CI / 2);
#pragma unroll
    for (int dn = 0; dn < 16; dn++) {
        uint i0 = row0 * 64 + dn * 4 + (lane & 3);
        uint i1 = i0 + 8 * 64;
        float v0 = o[dn][0] * inv0, v1 = o[dn][1] * inv0;
        float v2 = o[dn][2] * inv1, v3 = o[dn][3] * inv1;
        uint h0 = pack2(v0, v1), h1 = pack2(v2, v3);
        float e0 = v0 - __uint_as_float(h0 << 16);
        float e1 = v1 - __uint_as_float(h0 & 0xffff0000u);
        float e2 = v2 - __uint_as_float(h1 << 16);
        float e3 = v3 - __uint_as_float(h1 & 0xffff0000u);
        yh[i0] = h0; yl[i0] = pack2(e0, e1);
        yh[i1] = h1; yl[i1] = pack2(e2, e3);
    }
}

// ---------------- kernel 3: mma wgemm (ldmatrix) + fused BN partial stats ----------------
#define WG_YH 0
#define WG_YL 34816
#define WG_WH 69632
#define WG_WL 104448
#define WG_SMEM 139264

extern __shared__ char sm_w[];

__global__ void __launch_bounds__(256, 1) wgemm_kernel(const float* __restrict__ Wb)
{
    const int b  = blockIdx.z;
    const int oh = blockIdx.y;
    const int n0 = blockIdx.x * 128;
    const int tid = threadIdx.x;
    const int lane = tid & 31, warp = tid >> 5;
    const uint sb = smem_u32(sm_w);

    {
        const char* yh = (const char*)(g_Yh + (size_t)(b * NN + n0) * CI);
        const char* yl = (const char*)(g_Yl + (size_t)(b * NN + n0) * CI);
        const char* wh = (const char*)(g_Wwh + (size_t)(oh * 128) * CI);
        const char* wl = (const char*)(g_Wwl + (size_t)(oh * 128) * CI);
#pragma unroll
        for (int it = 0; it < 8; it++) {
            int u = tid + it * 256;
            int row = u >> 4, ch = u & 15;
            cpa16(sb + WG_YH + row * 272 + ch * 16, yh + (size_t)row * 256 + ch * 16);
            cpa16(sb + WG_YL + row * 272 + ch * 16, yl + (size_t)row * 256 + ch * 16);
            cpa16(sb + WG_WH + row * 272 + ch * 16, wh + (size_t)row * 256 + ch * 16);
            cpa16(sb + WG_WL + row * 272 + ch * 16, wl + (size_t)row * 256 + ch * 16);
        }
    }
    CP_COMMIT();
    CP_WAIT0();
    __syncthreads();

    const int r0 = warp * 16 + (lane >> 2);
    float acc[16][4];
#pragma unroll
    for (int i = 0; i < 16; i++)
#pragma unroll
        for (int c = 0; c < 4; c++) acc[i][c] = 0.f;

    const uint qoff = (uint)(warp * 16 + (lane & 15)) * 272 + ((lane >> 4) << 4);
    const uint koff = (uint)((lane & 7) + ((lane >> 4) << 3)) * 272 + (((lane >> 3) & 1) << 4);

#pragma unroll
    for (int kt = 0; kt < 8; kt++) {
        uint ah0, ah1, ah2, ah3, al0, al1, al2, al3;
        LDSM4(ah0, ah1, ah2, ah3, sb + WG_YH + qoff + kt * 32);
        LDSM4(al0, al1, al2, al3, sb + WG_YL + qoff + kt * 32);
#pragma unroll
        for (int op = 0; op < 8; op++) {
            uint bh0, bh1, bh2, bh3, bl0, bl1, bl2, bl3;
            LDSM4(bh0, bh1, bh2, bh3, sb + WG_WH + koff + (uint)op * 16 * 272 + kt * 32);
            LDSM4(bl0, bl1, bl2, bl3, sb + WG_WL + koff + (uint)op * 16 * 272 + kt * 32);
            mma_bf(acc[2*op][0], acc[2*op][1], acc[2*op][2], acc[2*op][3],
                   ah0, ah1, ah2, ah3, bh0, bh1);
            mma_bf(acc[2*op][0], acc[2*op][1], acc[2*op][2], acc[2*op][3],
                   ah0, ah1, ah2, ah3, bl0, bl1);
            mma_bf(acc[2*op][0], acc[2*op][1], acc[2*op][2], acc[2*op][3],
                   al0, al1, al2, al3, bh0, bh1);
            mma_bf(acc[2*op+1][0], acc[2*op+1][1], acc[2*op+1][2], acc[2*op+1][3],
                   ah0, ah1, ah2, ah3, bh2, bh3);
            mma_bf(acc[2*op+1][0], acc[2*op+1][1], acc[2*op+1][2], acc[2*op+1][3],
                   ah0, ah1, ah2, ah3, bl2, bl3);
            mma_bf(acc[2*op+1][0], acc[2*op+1][1], acc[2*op+1][2], acc[2*op+1][3],
                   al0, al1, al2, al3, bh2, bh3);
        }
    }

    // add bias into acc, store WY
    float* wy = g_WY + (size_t)(b * NN + n0) * CC + oh * 128;
#pragma unroll
    for (int ot = 0; ot < 16; ot++) {
        int o = ot * 8 + (lane & 3) * 2;
        float b0 = Wb[oh * 128 + o], b1 = Wb[oh * 128 + o + 1];
        acc[ot][0] += b0; acc[ot][1] += b1;
        acc[ot][2] += b0; acc[ot][3] += b1;
        *(float2*)(wy + (size_t)r0 * CC + o) = make_float2(acc[ot][0], acc[ot][1]);
        *(float2*)(wy + (size_t)(r0 + 8) * CC + o) = make_float2(acc[ot][2], acc[ot][3]);
    }

    // fused BN partial stats: column sums over this CTA's 128 rows
    __syncthreads();                       // smem tile reads done; reuse as reduction buffer
    float* ws_sum = (float*)sm_w;          // [8][128]
    float* ws_sq  = (float*)sm_w + 1024;   // [8][128]
#pragma unroll
    for (int ot = 0; ot < 16; ot++) {
        float s0 = acc[ot][0] + acc[ot][2];
        float s1 = acc[ot][1] + acc[ot][3];
        float q0 = acc[ot][0] * acc[ot][0] + acc[ot][2] * acc[ot][2];
        float q1 = acc[ot][1] * acc[ot][1] + acc[ot][3] * acc[ot][3];
#pragma unroll
        for (int off = 4; off <= 16; off <<= 1) {
            s0 += __shfl_xor_sync(0xffffffffu, s0, off);
            s1 += __shfl_xor_sync(0xffffffffu, s1, off);
            q0 += __shfl_xor_sync(0xffffffffu, q0, off);
            q1 += __shfl_xor_sync(0xffffffffu, q1, off);
        }
        if ((lane >> 2) == 0) {            // lanes 0-3 hold warp-level column sums
            int col = ot * 8 + lane * 2;
            ws_sum[warp * 128 + col] = s0;
            ws_sum[warp * 128 + col + 1] = s1;
            ws_sq[warp * 128 + col] = q0;
            ws_sq[warp * 128 + col + 1] = q1;
        }
    }
    __syncthreads();
    if (tid < 128) {
        float s = 0.f, q = 0.f;
#pragma unroll
        for (int w = 0; w < 8; w++) {
            s += ws_sum[w * 128 + tid];
            q += ws_sq[w * 128 + tid];
        }
        int slot = b * 32 + blockIdx.x;    // 128 slots, same grouping as before
        g_psum[slot * CC + oh * 128 + tid] = s;
        g_psq [slot * CC + oh * 128 + tid] = q;
    }
}

// ---------------- kernel 4: final BN stats ----------------
__global__ void __launch_bounds__(256) stats2_kernel()
{
    const int t = threadIdx.x;
    float s = 0.f, q = 0.f;
    for (int p = 0; p < 128; p++) {
        s += g_psum[p * CC + t];
        q += g_psq [p * CC + t];
    }
    const float invn = 1.0f / (float)(BB * NN);
    float mean = s * invn;
    float var  = q * invn - mean * mean;
    g_mean[t] = mean;
    g_rstd[t] = rsqrtf(var + BN_EPS);
}

// ---------------- kernel 5: BN apply + scale + residual (with transpose) ----------------
__global__ void __launch_bounds__(256) apply_kernel(
    const float* __restrict__ x,
    const float* __restrict__ gamma, const float* __restrict__ beta,
    const float* __restrict__ scale, float* __restrict__ out)
{
    __shared__ float st[64 * 65];
    const int n0 = blockIdx.x * 64;
    const int c0 = blockIdx.y * 64;
    const int b  = blockIdx.z;
    const int tid = threadIdx.x;
    const float s = scale[0];

#pragma unroll
    for (int r = 0; r < 16; r++) {
        int idx = tid + r * 256;
        int nl = idx >> 6, cc = idx & 63;
        st[cc * 65 + nl] = g_WY[((size_t)(b * NN + n0 + nl)) * CC + c0 + cc];
    }
    __syncthreads();
#pragma unroll
    for (int r = 0; r < 16; r++) {
        int idx = tid + r * 256;
        int cc = idx >> 6, nl = idx & 63;
        int c = c0 + cc;
        float wv = st[cc * 65 + nl];
        float v = s * ((wv - g_mean[c]) * g_rstd[c] * gamma[c] + beta[c])
                + x[((size_t)(b * CC + c)) * NN + n0 + nl];
        out[((size_t)(b * CC + c)) * NN + n0 + nl] = v;
    }
}

// ---------------- launcher ----------------
extern "C" void kernel_launch(void* const* d_in, const int* in_sizes, int n_in,
                              void* d_out, int out_size)
{
    const float* x     = (const float*)d_in[0];
    const float* gw    = (const float*)d_in[1];
    const float* gb    = (const float*)d_in[2];
    const float* tw    = (const float*)d_in[3];
    const float* tb    = (const float*)d_in[4];
    const float* pw    = (const float*)d_in[5];
    const float* pb    = (const float*)d_in[6];
    const float* Ww    = (const float*)d_in[7];
    const float* Wb    = (const float*)d_in[8];
    const float* gamma = (const float*)d_in[9];
    const float* beta  = (const float*)d_in[10];
    const float* scale = (const float*)d_in[11];
    float* out = (float*)d_out;

    cudaFuncSetAttribute(proj_kernel,
                         cudaFuncAttributeMaxDynamicSharedMemorySize, PROJ_SMEM);
    cudaFuncSetAttribute(attn_kernel,
                         cudaFuncAttributeMaxDynamicSharedMemorySize, ATTN_SMEM);
    cudaFuncSetAttribute(wgemm_kernel,
                         cudaFuncAttributeMaxDynamicSharedMemorySize, WG_SMEM);

    xcvt_kernel<<<dim3(NN / 64, CC / 64, BB), 256>>>(x);
    wcvt_kernel<<<64, 256>>>(gw, tw, pw, Ww);
    proj_kernel<<<dim3(NN / 128, BB, 3), 256, PROJ_SMEM>>>(gb, tb, pb);
    attn_kernel<<<dim3(NN / 128, BB), 256, ATTN_SMEM>>>();
    wgemm_kernel<<<dim3(NN / 128, 2, BB), 256, WG_SMEM>>>(Wb);
    stats2_kernel<<<1, 256>>>();
    apply_kernel<<<dim3(NN / 64, CC / 64, BB), 256>>>(x, gamma, beta, scale, out);
}